// round 3
// baseline (speedup 1.0000x reference)
#include <cuda_runtime.h>
#include <cstdint>
#include <cstddef>
#include <math.h>

#define NUSERS 16384
#define HDIM 512
#define LATENT 256
#define MAX_ITEMS 50176
#define MAX_N (1 << 19)

// ---------------- device scratch (no allocation allowed) ----------------
__device__ __align__(128) float g_WencT[(size_t)MAX_ITEMS * HDIM];
__device__ __align__(128) float g_x[(size_t)NUSERS * HDIM];
__device__ __align__(128) float g_enc[(size_t)NUSERS * LATENT];
__device__ __align__(128) float g_dec[(size_t)NUSERS * HDIM];
__device__ int   g_counts[NUSERS];
__device__ int   g_offsets[NUSERS + 1];
__device__ int   g_cursor[NUSERS];
__device__ int   g_idx[MAX_N];
__device__ int   g_bsum[128];
__device__ int   g_bsumx[128];
__device__ float g_partials[MAX_N / 8 + 64];

// ---------------- transpose W_enc [512][items] -> g_WencT [items][512] ----------------
__global__ void k_transpose(const float* __restrict__ W, int items) {
    __shared__ float tile[32][33];
    int i = blockIdx.x * 32 + threadIdx.x;
    int h = blockIdx.y * 32 + threadIdx.y;
    if (i < items)
        tile[threadIdx.y][threadIdx.x] = W[(size_t)h * items + i];
    __syncthreads();
    int io = blockIdx.x * 32 + threadIdx.y;
    int ho = blockIdx.y * 32 + threadIdx.x;
    if (io < items)
        g_WencT[(size_t)io * HDIM + ho] = tile[threadIdx.x][threadIdx.y];
}

// ---------------- bucketing ----------------
__global__ void k_init_counts() {
    int i = blockIdx.x * blockDim.x + threadIdx.x;
    if (i < NUSERS) g_counts[i] = 0;
}

__global__ void k_hist(const int* __restrict__ user, int n) {
    for (int i = blockIdx.x * blockDim.x + threadIdx.x; i < n; i += gridDim.x * blockDim.x)
        atomicAdd(&g_counts[user[i]], 1);
}

// 3-stage parallel exclusive scan of g_counts[16384]
__global__ void __launch_bounds__(128) k_scanA() {
    const int b = blockIdx.x, t = threadIdx.x;
    const int lane = t & 31, w = t >> 5;
    int v = g_counts[b * 128 + t];
    int inc = v;
#pragma unroll
    for (int off = 1; off < 32; off <<= 1) {
        int s = __shfl_up_sync(0xffffffffu, inc, off);
        if (lane >= off) inc += s;
    }
    __shared__ int ws[4];
    if (lane == 31) ws[w] = inc;
    __syncthreads();
    int wbase = 0;
#pragma unroll
    for (int i = 0; i < 4; i++) if (i < w) wbase += ws[i];
    g_offsets[b * 128 + t] = wbase + inc - v;   // local exclusive
    if (t == 127) g_bsum[b] = wbase + inc;      // block total
}

__global__ void __launch_bounds__(128) k_scanB() {
    const int t = threadIdx.x, lane = t & 31, w = t >> 5;
    int v = g_bsum[t];
    int inc = v;
#pragma unroll
    for (int off = 1; off < 32; off <<= 1) {
        int s = __shfl_up_sync(0xffffffffu, inc, off);
        if (lane >= off) inc += s;
    }
    __shared__ int ws[4];
    if (lane == 31) ws[w] = inc;
    __syncthreads();
    int wbase = 0;
#pragma unroll
    for (int i = 0; i < 4; i++) if (i < w) wbase += ws[i];
    g_bsumx[t] = wbase + inc - v;
}

__global__ void __launch_bounds__(128) k_scanC(int n) {
    const int b = blockIdx.x, t = threadIdx.x;
    const int i = b * 128 + t;
    int o = g_offsets[i] + g_bsumx[b];
    g_offsets[i] = o;
    g_cursor[i]  = o;
    if (i == 0) g_offsets[NUSERS] = n;
}

__global__ void k_scatter(const int* __restrict__ user, int n) {
    for (int i = blockIdx.x * blockDim.x + threadIdx.x; i < n; i += gridDim.x * blockDim.x) {
        int u = user[i];
        int pos = atomicAdd(&g_cursor[u], 1);
        g_idx[pos] = i;
    }
}

// ---------------- per-user segment sum + tanh(agg + b_enc) ----------------
__global__ void __launch_bounds__(128) k_aggregate(const int* __restrict__ item,
                                                   const float* __restrict__ rating,
                                                   const float* __restrict__ b_enc) {
    const int u = blockIdx.x;
    const int tid = threadIdx.x;
    const int beg = g_offsets[u], end = g_offsets[u + 1];
    __shared__ int   s_idx[512];
    __shared__ int   s_it[512];
    __shared__ float s_r[512];
    float4 acc = make_float4(0.f, 0.f, 0.f, 0.f);
    const int h4 = tid * 4;
    for (int ch = beg; ch < end; ch += 512) {
        int c = min(512, end - ch);
        for (int i = tid; i < c; i += 128) s_idx[i] = g_idx[ch + i];
        __syncthreads();
        if (tid == 0) {
            for (int i = 1; i < c; i++) {
                int key = s_idx[i];
                int j = i - 1;
                while (j >= 0 && s_idx[j] > key) { s_idx[j + 1] = s_idx[j]; j--; }
                s_idx[j + 1] = key;
            }
        }
        __syncthreads();
        for (int i = tid; i < c; i += 128) {
            int nn = s_idx[i];
            s_it[i] = item[nn];
            s_r[i]  = rating[nn];
        }
        __syncthreads();
        for (int e = 0; e < c; e++) {
            const float4 w = *reinterpret_cast<const float4*>(&g_WencT[(size_t)s_it[e] * HDIM + h4]);
            float r = s_r[e];
            acc.x += r * w.x; acc.y += r * w.y; acc.z += r * w.z; acc.w += r * w.w;
        }
        __syncthreads();
    }
    float4 b = *reinterpret_cast<const float4*>(&b_enc[h4]);
    float4 o = make_float4(tanhf(acc.x + b.x), tanhf(acc.y + b.y),
                           tanhf(acc.z + b.z), tanhf(acc.w + b.w));
    *reinterpret_cast<float4*>(&g_x[(size_t)u * HDIM + h4]) = o;
}

// ---------------- fused tanh GEMM, 128x128 tile, 8x8 microtile (2x2 of 4x4) ----------------
// C[m][n] = tanh(bias[n] + sum_k A[m][k] * W[n][k])
// SRC==0: A=g_x (K=512), C=g_enc (N=256). SRC==1: A=g_enc (K=256), C=g_dec (N=512).
template <int NCOLS, int KDIM, int SRC>
__global__ void __launch_bounds__(256, 2) k_gemm_tanh(const float* __restrict__ W,
                                                      const float* __restrict__ bias) {
    const float* A = (SRC == 0) ? g_x : g_enc;
    float* C       = (SRC == 0) ? g_enc : g_dec;
    __shared__ float As[16][132];
    __shared__ float Bs[16][132];
    const int tid = threadIdx.x;
    const int m0 = blockIdx.y * 128, n0 = blockIdx.x * 128;

    // global-load mapping: float4 index f -> row f>>2, kquad (f&3)*4 ; thread owns f=tid and f=tid+256
    const int fr = tid >> 2;
    const int fk = (tid & 3) << 2;
    const float* Ap0 = A + (size_t)(m0 + fr) * KDIM + fk;
    const float* Ap1 = A + (size_t)(m0 + fr + 64) * KDIM + fk;
    const float* Wp0 = W + (size_t)(n0 + fr) * KDIM + fk;
    const float* Wp1 = W + (size_t)(n0 + fr + 64) * KDIM + fk;

    const int tx = tid & 15, ty = tid >> 4;

    float4 pa0 = *reinterpret_cast<const float4*>(Ap0);
    float4 pa1 = *reinterpret_cast<const float4*>(Ap1);
    float4 pb0 = *reinterpret_cast<const float4*>(Wp0);
    float4 pb1 = *reinterpret_cast<const float4*>(Wp1);

    float acc[8][8];
#pragma unroll
    for (int i = 0; i < 8; i++)
#pragma unroll
        for (int j = 0; j < 8; j++) acc[i][j] = 0.f;

    for (int k0 = 0; k0 < KDIM; k0 += 16) {
        // deposit prefetched stage
        As[fk + 0][fr] = pa0.x; As[fk + 1][fr] = pa0.y; As[fk + 2][fr] = pa0.z; As[fk + 3][fr] = pa0.w;
        As[fk + 0][fr + 64] = pa1.x; As[fk + 1][fr + 64] = pa1.y; As[fk + 2][fr + 64] = pa1.z; As[fk + 3][fr + 64] = pa1.w;
        Bs[fk + 0][fr] = pb0.x; Bs[fk + 1][fr] = pb0.y; Bs[fk + 2][fr] = pb0.z; Bs[fk + 3][fr] = pb0.w;
        Bs[fk + 0][fr + 64] = pb1.x; Bs[fk + 1][fr + 64] = pb1.y; Bs[fk + 2][fr + 64] = pb1.z; Bs[fk + 3][fr + 64] = pb1.w;
        __syncthreads();

        // prefetch next stage (overlaps with compute below)
        if (k0 + 16 < KDIM) {
            pa0 = *reinterpret_cast<const float4*>(Ap0 + k0 + 16);
            pa1 = *reinterpret_cast<const float4*>(Ap1 + k0 + 16);
            pb0 = *reinterpret_cast<const float4*>(Wp0 + k0 + 16);
            pb1 = *reinterpret_cast<const float4*>(Wp1 + k0 + 16);
        }

#pragma unroll
        for (int k = 0; k < 16; k++) {
            float a[8], b[8];
            *reinterpret_cast<float4*>(&a[0]) = *reinterpret_cast<const float4*>(&As[k][ty * 4]);
            *reinterpret_cast<float4*>(&a[4]) = *reinterpret_cast<const float4*>(&As[k][64 + ty * 4]);
            *reinterpret_cast<float4*>(&b[0]) = *reinterpret_cast<const float4*>(&Bs[k][tx * 4]);
            *reinterpret_cast<float4*>(&b[4]) = *reinterpret_cast<const float4*>(&Bs[k][64 + tx * 4]);
#pragma unroll
            for (int i = 0; i < 8; i++)
#pragma unroll
                for (int j = 0; j < 8; j++) acc[i][j] += a[i] * b[j];
        }
        __syncthreads();
    }

    // epilogue: bias + tanh, vectorized stores
    float bcol[8];
#pragma unroll
    for (int jh = 0; jh < 2; jh++)
#pragma unroll
        for (int j = 0; j < 4; j++) bcol[jh * 4 + j] = bias[n0 + jh * 64 + tx * 4 + j];

#pragma unroll
    for (int ih = 0; ih < 2; ih++) {
#pragma unroll
        for (int i = 0; i < 4; i++) {
            int m = m0 + ih * 64 + ty * 4 + i;
#pragma unroll
            for (int jh = 0; jh < 2; jh++) {
                float4 v;
                v.x = tanhf(acc[ih * 4 + i][jh * 4 + 0] + bcol[jh * 4 + 0]);
                v.y = tanhf(acc[ih * 4 + i][jh * 4 + 1] + bcol[jh * 4 + 1]);
                v.z = tanhf(acc[ih * 4 + i][jh * 4 + 2] + bcol[jh * 4 + 2]);
                v.w = tanhf(acc[ih * 4 + i][jh * 4 + 3] + bcol[jh * 4 + 3]);
                *reinterpret_cast<float4*>(&C[(size_t)m * NCOLS + n0 + jh * 64 + tx * 4]) = v;
            }
        }
    }
}

// ---------------- prediction + per-block squared-error partials ----------------
__global__ void __launch_bounds__(256) k_pred(const int* __restrict__ tu,
                                              const int* __restrict__ ti,
                                              const float* __restrict__ tr,
                                              const float* __restrict__ Wdec,
                                              const float* __restrict__ bdec,
                                              float* __restrict__ out, int nt) {
    __shared__ float sh[8];
    const int gw = (blockIdx.x * 256 + threadIdx.x) >> 5;
    const int lane = threadIdx.x & 31;
    float se = 0.f;
    if (gw < nt) {
        int u  = tu[gw];
        int it = ti[gw];
        const float4* g = reinterpret_cast<const float4*>(&g_dec[(size_t)u * HDIM]);
        const float4* w = reinterpret_cast<const float4*>(&Wdec[(size_t)it * HDIM]);
        float s = 0.f;
#pragma unroll
        for (int q = 0; q < 4; q++) {
            float4 a = g[lane + 32 * q];
            float4 b = w[lane + 32 * q];
            s += a.x * b.x + a.y * b.y + a.z * b.z + a.w * b.w;
        }
#pragma unroll
        for (int off = 16; off; off >>= 1) s += __shfl_down_sync(0xffffffffu, s, off);
        if (lane == 0) {
            float p = s + bdec[it];
            out[gw] = p;
            float d = p - tr[gw];
            se = d * d;
        }
    }
    if (lane == 0) sh[threadIdx.x >> 5] = se;
    __syncthreads();
    if (threadIdx.x == 0) {
        float t = 0.f;
#pragma unroll
        for (int i = 0; i < 8; i++) t += sh[i];
        g_partials[blockIdx.x] = t;
    }
}

__global__ void __launch_bounds__(1024) k_loss(float* __restrict__ loc, int nblocks, int nt) {
    __shared__ float sh[32];
    const int tid = threadIdx.x;
    float s = 0.f;
    for (int i = tid; i < nblocks; i += 1024) s += g_partials[i];
#pragma unroll
    for (int off = 16; off; off >>= 1) s += __shfl_down_sync(0xffffffffu, s, off);
    if ((tid & 31) == 0) sh[tid >> 5] = s;
    __syncthreads();
    if (tid < 32) {
        float v = sh[tid];
#pragma unroll
        for (int off = 16; off; off >>= 1) v += __shfl_down_sync(0xffffffffu, v, off);
        if (tid == 0) *loc = v / (float)nt;
    }
}

// ---------------- launch ----------------
extern "C" void kernel_launch(void* const* d_in, const int* in_sizes, int n_in,
                              void* d_out, int out_size) {
    const int*   user   = (const int*)d_in[0];
    const int*   item   = (const int*)d_in[1];
    const float* rating = (const float*)d_in[2];
    const int*   tuser  = (const int*)d_in[3];
    const int*   titem  = (const int*)d_in[4];
    const float* trat   = (const float*)d_in[5];
    const float* W_enc  = (const float*)d_in[6];
    const float* b_enc  = (const float*)d_in[7];
    const float* W1     = (const float*)d_in[8];
    const float* b1     = (const float*)d_in[9];
    const float* W2     = (const float*)d_in[10];
    const float* b2     = (const float*)d_in[11];
    const float* W_dec  = (const float*)d_in[12];
    const float* b_dec  = (const float*)d_in[13];

    const int N     = in_sizes[0];
    const int NT    = in_sizes[3];
    const int items = in_sizes[13];

    float* pred = (float*)d_out;

    // 1. transpose encoder weights
    k_transpose<<<dim3((items + 31) / 32, HDIM / 32), dim3(32, 32)>>>(W_enc, items);

    // 2. bucket interactions by user
    k_init_counts<<<64, 256>>>();
    k_hist<<<256, 256>>>(user, N);
    k_scanA<<<128, 128>>>();
    k_scanB<<<1, 128>>>();
    k_scanC<<<128, 128>>>(N);
    k_scatter<<<256, 256>>>(user, N);

    // 3. per-user segment sum + tanh(+b_enc)
    k_aggregate<<<NUSERS, 128>>>(item, rating, b_enc);

    // 4. encoder / decoder tanh GEMMs
    k_gemm_tanh<LATENT, HDIM, 0><<<dim3(LATENT / 128, NUSERS / 128), 256>>>(W1, b1);
    k_gemm_tanh<HDIM, LATENT, 1><<<dim3(HDIM / 128, NUSERS / 128), 256>>>(W2, b2);

    // 5. predictions + loss partials
    const int npb = (NT + 7) / 8;
    k_pred<<<npb, 256>>>(tuser, titem, trat, W_dec, b_dec, pred, NT);

    // 6. final loss
    if (out_size > NT)
        k_loss<<<1, 1024>>>(pred + NT, npb, NT);
}

// round 5
// speedup vs baseline: 1.1786x; 1.1786x over previous
#include <cuda_runtime.h>
#include <cuda_bf16.h>
#include <cstdint>
#include <cstddef>
#include <math.h>

#define NUSERS 16384
#define HDIM 512
#define LATENT 256
#define MAX_ITEMS 50176
#define MAX_N (1 << 19)

// ---------------- device scratch (no allocation allowed) ----------------
__device__ __align__(128) float g_WencT[(size_t)MAX_ITEMS * HDIM];
__device__ __align__(128) __nv_bfloat16 g_xs[(size_t)NUSERS * (2 * HDIM)];     // [xh(512) | xl(512)]
__device__ __align__(128) __nv_bfloat16 g_encs[(size_t)NUSERS * (2 * LATENT)]; // [eh(256) | el(256)]
__device__ __align__(128) __nv_bfloat16 g_W1s[(size_t)LATENT * (3 * HDIM)];    // [wh | wl | wh]
__device__ __align__(128) __nv_bfloat16 g_W2s[(size_t)HDIM * (3 * LATENT)];
__device__ __align__(128) float g_dec[(size_t)NUSERS * HDIM];
__device__ int   g_counts[NUSERS];
__device__ int   g_offsets[NUSERS + 1];
__device__ int   g_cursor[NUSERS];
__device__ int   g_idx[MAX_N];
__device__ int   g_bsum[128];
__device__ int   g_bsumx[128];
__device__ float g_partials[MAX_N / 8 + 64];

// ---------------- PTX helpers (arch-neutral: sm_80+ features only) ----------------
__device__ __forceinline__ uint32_t smem_u32(const void* p) {
    uint32_t a;
    asm("{ .reg .u64 t; cvta.to.shared.u64 t, %1; cvt.u32.u64 %0, t; }" : "=r"(a) : "l"(p));
    return a;
}
__device__ __forceinline__ void cpasync16(uint32_t dst, const void* src) {
    asm volatile("cp.async.cg.shared.global [%0], [%1], 16;" :: "r"(dst), "l"(src) : "memory");
}
__device__ __forceinline__ void cp_commit() {
    asm volatile("cp.async.commit_group;" ::: "memory");
}
template <int NREM>
__device__ __forceinline__ void cp_wait() {
    asm volatile("cp.async.wait_group %0;" :: "n"(NREM) : "memory");
}
__device__ __forceinline__ void ldsm_x4(uint32_t& r0, uint32_t& r1, uint32_t& r2, uint32_t& r3,
                                        uint32_t addr) {
    asm volatile("ldmatrix.sync.aligned.m8n8.x4.shared.b16 {%0,%1,%2,%3}, [%4];"
                 : "=r"(r0), "=r"(r1), "=r"(r2), "=r"(r3) : "r"(addr));
}
__device__ __forceinline__ void mma_bf16(float* c, uint32_t a0, uint32_t a1, uint32_t a2, uint32_t a3,
                                         uint32_t b0, uint32_t b1) {
    asm volatile("mma.sync.aligned.m16n8k16.row.col.f32.bf16.bf16.f32 "
                 "{%0,%1,%2,%3}, {%4,%5,%6,%7}, {%8,%9}, {%0,%1,%2,%3};"
                 : "+f"(c[0]), "+f"(c[1]), "+f"(c[2]), "+f"(c[3])
                 : "r"(a0), "r"(a1), "r"(a2), "r"(a3), "r"(b0), "r"(b1));
}

// ---------------- transpose W_enc [512][items] -> g_WencT [items][512] ----------------
__global__ void k_transpose(const float* __restrict__ W, int items) {
    __shared__ float tile[32][33];
    int i = blockIdx.x * 32 + threadIdx.x;
    int h = blockIdx.y * 32 + threadIdx.y;
    if (i < items)
        tile[threadIdx.y][threadIdx.x] = W[(size_t)h * items + i];
    __syncthreads();
    int io = blockIdx.x * 32 + threadIdx.y;
    int ho = blockIdx.y * 32 + threadIdx.x;
    if (io < items)
        g_WencT[(size_t)io * HDIM + ho] = tile[threadIdx.x][threadIdx.y];
}

// ---------------- split weights into [hi | lo | hi] bf16 ----------------
__global__ void k_split_w(const float* __restrict__ W, __nv_bfloat16* __restrict__ out, int total, int k) {
    int i = blockIdx.x * 256 + threadIdx.x;
    if (i >= total) return;
    int r = i / k, c = i % k;
    float v = W[i];
    __nv_bfloat16 h = __float2bfloat16(v);
    __nv_bfloat16 l = __float2bfloat16(v - __bfloat162float(h));
    size_t base = (size_t)r * 3 * k;
    out[base + c] = h;
    out[base + k + c] = l;
    out[base + 2 * k + c] = h;
}

// ---------------- bucketing ----------------
__global__ void k_init_counts() {
    int i = blockIdx.x * blockDim.x + threadIdx.x;
    if (i < NUSERS) g_counts[i] = 0;
}

__global__ void k_hist(const int* __restrict__ user, int n) {
    for (int i = blockIdx.x * blockDim.x + threadIdx.x; i < n; i += gridDim.x * blockDim.x)
        atomicAdd(&g_counts[user[i]], 1);
}

__global__ void __launch_bounds__(128) k_scanA() {
    const int b = blockIdx.x, t = threadIdx.x;
    const int lane = t & 31, w = t >> 5;
    int v = g_counts[b * 128 + t];
    int inc = v;
#pragma unroll
    for (int off = 1; off < 32; off <<= 1) {
        int s = __shfl_up_sync(0xffffffffu, inc, off);
        if (lane >= off) inc += s;
    }
    __shared__ int ws[4];
    if (lane == 31) ws[w] = inc;
    __syncthreads();
    int wbase = 0;
#pragma unroll
    for (int i = 0; i < 4; i++) if (i < w) wbase += ws[i];
    g_offsets[b * 128 + t] = wbase + inc - v;
    if (t == 127) g_bsum[b] = wbase + inc;
}

__global__ void __launch_bounds__(128) k_scanB() {
    const int t = threadIdx.x, lane = t & 31, w = t >> 5;
    int v = g_bsum[t];
    int inc = v;
#pragma unroll
    for (int off = 1; off < 32; off <<= 1) {
        int s = __shfl_up_sync(0xffffffffu, inc, off);
        if (lane >= off) inc += s;
    }
    __shared__ int ws[4];
    if (lane == 31) ws[w] = inc;
    __syncthreads();
    int wbase = 0;
#pragma unroll
    for (int i = 0; i < 4; i++) if (i < w) wbase += ws[i];
    g_bsumx[t] = wbase + inc - v;
}

__global__ void __launch_bounds__(128) k_scanC(int n) {
    const int b = blockIdx.x, t = threadIdx.x;
    const int i = b * 128 + t;
    int o = g_offsets[i] + g_bsumx[b];
    g_offsets[i] = o;
    g_cursor[i]  = o;
    if (i == 0) g_offsets[NUSERS] = n;
}

__global__ void k_scatter(const int* __restrict__ user, int n) {
    for (int i = blockIdx.x * blockDim.x + threadIdx.x; i < n; i += gridDim.x * blockDim.x) {
        int u = user[i];
        int pos = atomicAdd(&g_cursor[u], 1);
        g_idx[pos] = i;
    }
}

// ---------------- per-user segment sum + tanh(agg + b_enc) -> bf16 hi/lo ----------------
__global__ void __launch_bounds__(128) k_aggregate(const int* __restrict__ item,
                                                   const float* __restrict__ rating,
                                                   const float* __restrict__ b_enc) {
    const int u = blockIdx.x;
    const int tid = threadIdx.x;
    const int beg = g_offsets[u], end = g_offsets[u + 1];
    __shared__ int   s_idx[512];
    __shared__ int   s_it[512];
    __shared__ float s_r[512];
    float4 acc = make_float4(0.f, 0.f, 0.f, 0.f);
    const int h4 = tid * 4;
    for (int ch = beg; ch < end; ch += 512) {
        int c = min(512, end - ch);
        for (int i = tid; i < c; i += 128) s_idx[i] = g_idx[ch + i];
        __syncthreads();
        if (tid == 0) {
            for (int i = 1; i < c; i++) {
                int key = s_idx[i];
                int j = i - 1;
                while (j >= 0 && s_idx[j] > key) { s_idx[j + 1] = s_idx[j]; j--; }
                s_idx[j + 1] = key;
            }
        }
        __syncthreads();
        for (int i = tid; i < c; i += 128) {
            int nn = s_idx[i];
            s_it[i] = item[nn];
            s_r[i]  = rating[nn];
        }
        __syncthreads();
        for (int e = 0; e < c; e++) {
            const float4 w = *reinterpret_cast<const float4*>(&g_WencT[(size_t)s_it[e] * HDIM + h4]);
            float r = s_r[e];
            acc.x += r * w.x; acc.y += r * w.y; acc.z += r * w.z; acc.w += r * w.w;
        }
        __syncthreads();
    }
    float4 b = *reinterpret_cast<const float4*>(&b_enc[h4]);
    float t[4] = { tanhf(acc.x + b.x), tanhf(acc.y + b.y), tanhf(acc.z + b.z), tanhf(acc.w + b.w) };
    __nv_bfloat16 hv[4], lv[4];
#pragma unroll
    for (int j = 0; j < 4; j++) {
        hv[j] = __float2bfloat16(t[j]);
        lv[j] = __float2bfloat16(t[j] - __bfloat162float(hv[j]));
    }
    *reinterpret_cast<uint2*>(&g_xs[(size_t)u * 1024 + h4])       = *reinterpret_cast<uint2*>(hv);
    *reinterpret_cast<uint2*>(&g_xs[(size_t)u * 1024 + 512 + h4]) = *reinterpret_cast<uint2*>(lv);
}

// ---------------- mma.sync split-bf16 GEMM ----------------
// D[m, n] = tanh(bias[n] + 3-term-split A[m,:] . W'[n,:])
// A global: [M, ASTRIDE] bf16 = [hi(KDIM) | lo(KDIM)].  B global: [NTOT, 3*KDIM] = [wh|wl|wh].
// CTA tile 128x128, BK=32, 256 threads = 8 warps (4 m x 2 n), warp tile 32x64.
// OUTMODE 0: bf16 hi/lo pair -> Cb [M, 2*NTOT].  OUTMODE 1: fp32 -> Cf [M, NTOT].
#define SROW 40   // smem row stride in bf16 elements (80B, conflict-free for ldmatrix)
#define STAGE_B (128 * SROW * 2)  // bytes per stage

template <int KDIM, int ASTRIDE>
__device__ __forceinline__ void load_stage(const __nv_bfloat16* __restrict__ Ag,
                                           const __nv_bfloat16* __restrict__ Bg,
                                           int m0, int n0, int lr, int lg,
                                           uint32_t aBase, uint32_t bBase, int c, int s) {
    constexpr int KP = KDIM / 32;
    constexpr int BSTRIDE = 3 * KDIM;
    const int part = (c >= 2 * KP) ? 1 : 0;
    const int kofs = (c % KP) * 32;
    const __nv_bfloat16* Ap = Ag + (size_t)(m0 + lr) * ASTRIDE + part * KDIM + kofs + lg * 8;
    const __nv_bfloat16* Bp = Bg + (size_t)(n0 + lr) * BSTRIDE + c * 32 + lg * 8;
    uint32_t da = aBase + s * STAGE_B + (lr * SROW + lg * 8) * 2;
    uint32_t db = bBase + s * STAGE_B + (lr * SROW + lg * 8) * 2;
    cpasync16(da, Ap);      cpasync16(da + 16, Ap + 8);
    cpasync16(db, Bp);      cpasync16(db + 16, Bp + 8);
}

template <int KDIM, int ASTRIDE, int OUTMODE, int NTOT>
__global__ void __launch_bounds__(256) k_mma_gemm(const __nv_bfloat16* __restrict__ Ag,
                                                  const __nv_bfloat16* __restrict__ Bg,
                                                  const float* __restrict__ bias,
                                                  float* __restrict__ Cf,
                                                  __nv_bfloat16* __restrict__ Cb) {
    constexpr int NCH = 3 * (KDIM / 32);
    __shared__ __align__(1024) __nv_bfloat16 sA[2][128 * SROW];
    __shared__ __align__(1024) __nv_bfloat16 sB[2][128 * SROW];

    const int tid = threadIdx.x;
    const int wid = tid >> 5, lane = tid & 31;
    const int wm = wid & 3, wn = wid >> 2;
    const int m0 = blockIdx.y * 128, n0 = blockIdx.x * 128;
    const int lr = tid >> 1;            // loader row 0..127
    const int lg = (tid & 1) * 2;       // loader quad base

    const uint32_t aBase = smem_u32(sA), bBase = smem_u32(sB);

    // ldmatrix lane addressing (byte offsets within a stage)
    const int aRow = wm * 32 + (lane & 15);             // + mt*16
    const int aKB  = (lane >> 4) * 16;                  // k-half bytes
    const int bRow = wn * 64 + ((lane >> 4) * 8) + (lane & 7);   // + nt2*16
    const int bKB  = ((lane >> 3) & 1) * 16;

    float acc[2][8][4];
#pragma unroll
    for (int i = 0; i < 2; i++)
#pragma unroll
        for (int j = 0; j < 8; j++)
#pragma unroll
            for (int q = 0; q < 4; q++) acc[i][j][q] = 0.f;

    load_stage<KDIM, ASTRIDE>(Ag, Bg, m0, n0, lr, lg, aBase, bBase, 0, 0);
    cp_commit();

    for (int c = 0; c < NCH; c++) {
        const int s = c & 1;
        if (c + 1 < NCH) {
            load_stage<KDIM, ASTRIDE>(Ag, Bg, m0, n0, lr, lg, aBase, bBase, c + 1, s ^ 1);
            cp_commit();
            cp_wait<1>();
        } else {
            cp_wait<0>();
        }
        __syncthreads();

#pragma unroll
        for (int ks = 0; ks < 2; ks++) {
            uint32_t a[2][4];
#pragma unroll
            for (int mt = 0; mt < 2; mt++) {
                uint32_t addr = aBase + s * STAGE_B + ((aRow + mt * 16) * SROW) * 2 + ks * 32 + aKB;
                ldsm_x4(a[mt][0], a[mt][1], a[mt][2], a[mt][3], addr);
            }
            uint32_t b[8][2];
#pragma unroll
            for (int nt2 = 0; nt2 < 4; nt2++) {
                uint32_t addr = bBase + s * STAGE_B + ((bRow + nt2 * 16) * SROW) * 2 + ks * 32 + bKB;
                ldsm_x4(b[2 * nt2][0], b[2 * nt2][1], b[2 * nt2 + 1][0], b[2 * nt2 + 1][1], addr);
            }
#pragma unroll
            for (int mt = 0; mt < 2; mt++)
#pragma unroll
                for (int nt = 0; nt < 8; nt++)
                    mma_bf16(acc[mt][nt], a[mt][0], a[mt][1], a[mt][2], a[mt][3],
                             b[nt][0], b[nt][1]);
        }
        __syncthreads();
    }

    // epilogue
#pragma unroll
    for (int mt = 0; mt < 2; mt++) {
        const int mA = m0 + wm * 32 + mt * 16 + (lane >> 2);
#pragma unroll
        for (int nt = 0; nt < 8; nt++) {
            const int col = n0 + wn * 64 + nt * 8 + 2 * (lane & 3);
            const float b0 = __ldg(&bias[col]), b1 = __ldg(&bias[col + 1]);
#pragma unroll
            for (int half = 0; half < 2; half++) {
                const int m = mA + half * 8;
                const float t0 = tanhf(acc[mt][nt][2 * half + 0] + b0);
                const float t1 = tanhf(acc[mt][nt][2 * half + 1] + b1);
                if (OUTMODE == 0) {
                    __nv_bfloat16 h0 = __float2bfloat16(t0), h1 = __float2bfloat16(t1);
                    __nv_bfloat16 l0 = __float2bfloat16(t0 - __bfloat162float(h0));
                    __nv_bfloat16 l1 = __float2bfloat16(t1 - __bfloat162float(h1));
                    __nv_bfloat162 hp; hp.x = h0; hp.y = h1;
                    __nv_bfloat162 lp; lp.x = l0; lp.y = l1;
                    *reinterpret_cast<__nv_bfloat162*>(&Cb[(size_t)m * (2 * NTOT) + col]) = hp;
                    *reinterpret_cast<__nv_bfloat162*>(&Cb[(size_t)m * (2 * NTOT) + NTOT + col]) = lp;
                } else {
                    float2 v; v.x = t0; v.y = t1;
                    *reinterpret_cast<float2*>(&Cf[(size_t)m * NTOT + col]) = v;
                }
            }
        }
    }
}

// ---------------- prediction + per-block squared-error partials ----------------
__global__ void __launch_bounds__(256) k_pred(const int* __restrict__ tu,
                                              const int* __restrict__ ti,
                                              const float* __restrict__ tr,
                                              const float* __restrict__ Wdec,
                                              const float* __restrict__ bdec,
                                              float* __restrict__ out, int nt) {
    __shared__ float sh[8];
    const int gw = (blockIdx.x * 256 + threadIdx.x) >> 5;
    const int lane = threadIdx.x & 31;
    float se = 0.f;
    if (gw < nt) {
        int u  = tu[gw];
        int it = ti[gw];
        const float4* g = reinterpret_cast<const float4*>(&g_dec[(size_t)u * HDIM]);
        const float4* w = reinterpret_cast<const float4*>(&Wdec[(size_t)it * HDIM]);
        float s = 0.f;
#pragma unroll
        for (int q = 0; q < 4; q++) {
            float4 a = g[lane + 32 * q];
            float4 b = w[lane + 32 * q];
            s += a.x * b.x + a.y * b.y + a.z * b.z + a.w * b.w;
        }
#pragma unroll
        for (int off = 16; off; off >>= 1) s += __shfl_down_sync(0xffffffffu, s, off);
        if (lane == 0) {
            float p = s + bdec[it];
            out[gw] = p;
            float d = p - tr[gw];
            se = d * d;
        }
    }
    if (lane == 0) sh[threadIdx.x >> 5] = se;
    __syncthreads();
    if (threadIdx.x == 0) {
        float t = 0.f;
#pragma unroll
        for (int i = 0; i < 8; i++) t += sh[i];
        g_partials[blockIdx.x] = t;
    }
}

__global__ void __launch_bounds__(1024) k_loss(float* __restrict__ loc, int nblocks, int nt) {
    __shared__ float sh[32];
    const int tid = threadIdx.x;
    float s = 0.f;
    for (int i = tid; i < nblocks; i += 1024) s += g_partials[i];
#pragma unroll
    for (int off = 16; off; off >>= 1) s += __shfl_down_sync(0xffffffffu, s, off);
    if ((tid & 31) == 0) sh[tid >> 5] = s;
    __syncthreads();
    if (tid < 32) {
        float v = sh[tid];
#pragma unroll
        for (int off = 16; off; off >>= 1) v += __shfl_down_sync(0xffffffffu, v, off);
        if (tid == 0) *loc = v / (float)nt;
    }
}

// ---------------- launch ----------------
extern "C" void kernel_launch(void* const* d_in, const int* in_sizes, int n_in,
                              void* d_out, int out_size) {
    const int*   user   = (const int*)d_in[0];
    const int*   item   = (const int*)d_in[1];
    const float* rating = (const float*)d_in[2];
    const int*   tuser  = (const int*)d_in[3];
    const int*   titem  = (const int*)d_in[4];
    const float* trat   = (const float*)d_in[5];
    const float* W_enc  = (const float*)d_in[6];
    const float* b_enc  = (const float*)d_in[7];
    const float* W1     = (const float*)d_in[8];
    const float* b1     = (const float*)d_in[9];
    const float* W2     = (const float*)d_in[10];
    const float* b2     = (const float*)d_in[11];
    const float* W_dec  = (const float*)d_in[12];
    const float* b_dec  = (const float*)d_in[13];

    const int N     = in_sizes[0];
    const int NT    = in_sizes[3];
    const int items = in_sizes[13];

    float* pred = (float*)d_out;

    // 1. transpose encoder weights + split MLP weights to bf16 hi/lo
    k_transpose<<<dim3((items + 31) / 32, HDIM / 32), dim3(32, 32)>>>(W_enc, items);
    {
        __nv_bfloat16* w1s; cudaGetSymbolAddress((void**)&w1s, g_W1s);
        __nv_bfloat16* w2s; cudaGetSymbolAddress((void**)&w2s, g_W2s);
        k_split_w<<<(LATENT * HDIM + 255) / 256, 256>>>(W1, w1s, LATENT * HDIM, HDIM);
        k_split_w<<<(HDIM * LATENT + 255) / 256, 256>>>(W2, w2s, HDIM * LATENT, LATENT);
    }

    // 2. bucket interactions by user
    k_init_counts<<<64, 256>>>();
    k_hist<<<256, 256>>>(user, N);
    k_scanA<<<128, 128>>>();
    k_scanB<<<1, 128>>>();
    k_scanC<<<128, 128>>>(N);
    k_scatter<<<256, 256>>>(user, N);

    // 3. per-user segment sum + tanh(+b_enc) -> bf16 hi/lo
    k_aggregate<<<NUSERS, 128>>>(item, rating, b_enc);

    // 4. tensor-core (HMMA) split-bf16 GEMMs
    {
        __nv_bfloat16 *xs, *encs, *w1s, *w2s;
        float* dec;
        cudaGetSymbolAddress((void**)&xs,   g_xs);
        cudaGetSymbolAddress((void**)&encs, g_encs);
        cudaGetSymbolAddress((void**)&w1s,  g_W1s);
        cudaGetSymbolAddress((void**)&w2s,  g_W2s);
        cudaGetSymbolAddress((void**)&dec,  g_dec);
        // GEMM1: [16384,512] x [256,512]^T -> enc (bf16 hi/lo out)
        k_mma_gemm<HDIM, 2 * HDIM, 0, LATENT><<<dim3(LATENT / 128, NUSERS / 128), 256>>>(
            xs, w1s, b1, nullptr, encs);
        // GEMM2: [16384,256] x [512,256]^T -> dec (fp32 out)
        k_mma_gemm<LATENT, 2 * LATENT, 1, HDIM><<<dim3(HDIM / 128, NUSERS / 128), 256>>>(
            encs, w2s, b2, dec, nullptr);
    }

    // 5. predictions + loss partials
    const int npb = (NT + 7) / 8;
    k_pred<<<npb, 256>>>(tuser, titem, trat, W_dec, b_dec, pred, NT);

    // 6. final loss
    if (out_size > NT)
        k_loss<<<1, 1024>>>(pred + NT, npb, NT);
}

// round 8
// speedup vs baseline: 1.4788x; 1.2547x over previous
#include <cuda_runtime.h>
#include <cuda_bf16.h>
#include <cuda_fp16.h>
#include <cstdint>
#include <cstddef>
#include <math.h>

#define NUSERS 16384
#define HDIM 512
#define LATENT 256
#define MAX_ITEMS 50176
#define MAX_N (1 << 19)

// ---------------- device scratch (no allocation allowed) ----------------
__device__ __align__(128) float g_WencT[(size_t)MAX_ITEMS * HDIM];
__device__ __align__(128) __nv_bfloat16 g_xs[(size_t)NUSERS * (2 * HDIM)];     // [xh(512) | xl(512)]
__device__ __align__(128) __nv_bfloat16 g_encs[(size_t)NUSERS * (2 * LATENT)]; // [eh(256) | el(256)]
__device__ __align__(128) __nv_bfloat16 g_W1s[(size_t)LATENT * (3 * HDIM)];    // [wh | wl | wh]
__device__ __align__(128) __nv_bfloat16 g_W2s[(size_t)HDIM * (3 * LATENT)];
__device__ __align__(128) __half g_dec16[(size_t)NUSERS * HDIM];
__device__ __align__(128) __half g_Wdec16[(size_t)MAX_ITEMS * HDIM];
__device__ int   g_counts[NUSERS];
__device__ int   g_offsets[NUSERS + 1];
__device__ int   g_cursor[NUSERS];
__device__ int   g_idx[MAX_N];
__device__ int   g_bsum[128];
__device__ int   g_bsumx[128];
__device__ float g_partials[MAX_N / 8 + 64];

// ---------------- PTX helpers (arch-neutral: sm_80+ features only) ----------------
__device__ __forceinline__ uint32_t smem_u32(const void* p) {
    uint32_t a;
    asm("{ .reg .u64 t; cvta.to.shared.u64 t, %1; cvt.u32.u64 %0, t; }" : "=r"(a) : "l"(p));
    return a;
}
__device__ __forceinline__ void cpasync16(uint32_t dst, const void* src) {
    asm volatile("cp.async.cg.shared.global [%0], [%1], 16;" :: "r"(dst), "l"(src) : "memory");
}
__device__ __forceinline__ void cp_commit() {
    asm volatile("cp.async.commit_group;" ::: "memory");
}
template <int NREM>
__device__ __forceinline__ void cp_wait() {
    asm volatile("cp.async.wait_group %0;" :: "n"(NREM) : "memory");
}
__device__ __forceinline__ void ldsm_x4(uint32_t& r0, uint32_t& r1, uint32_t& r2, uint32_t& r3,
                                        uint32_t addr) {
    asm volatile("ldmatrix.sync.aligned.m8n8.x4.shared.b16 {%0,%1,%2,%3}, [%4];"
                 : "=r"(r0), "=r"(r1), "=r"(r2), "=r"(r3) : "r"(addr));
}
__device__ __forceinline__ void mma_bf16(float* c, uint32_t a0, uint32_t a1, uint32_t a2, uint32_t a3,
                                         uint32_t b0, uint32_t b1) {
    asm volatile("mma.sync.aligned.m16n8k16.row.col.f32.bf16.bf16.f32 "
                 "{%0,%1,%2,%3}, {%4,%5,%6,%7}, {%8,%9}, {%0,%1,%2,%3};"
                 : "+f"(c[0]), "+f"(c[1]), "+f"(c[2]), "+f"(c[3])
                 : "r"(a0), "r"(a1), "r"(a2), "r"(a3), "r"(b0), "r"(b1));
}

// ---------------- transpose W_enc [512][items] -> g_WencT [items][512] ----------------
__global__ void k_transpose(const float* __restrict__ W, int items) {
    __shared__ float tile[32][33];
    int i = blockIdx.x * 32 + threadIdx.x;
    int h = blockIdx.y * 32 + threadIdx.y;
    if (i < items)
        tile[threadIdx.y][threadIdx.x] = W[(size_t)h * items + i];
    __syncthreads();
    int io = blockIdx.x * 32 + threadIdx.y;
    int ho = blockIdx.y * 32 + threadIdx.x;
    if (io < items)
        g_WencT[(size_t)io * HDIM + ho] = tile[threadIdx.x][threadIdx.y];
}

// ---------------- fused prep: zero counts, split W1/W2 to bf16 hi/lo, Wdec -> fp16 -------
__device__ __forceinline__ void split_one(const float* __restrict__ W,
                                          __nv_bfloat16* __restrict__ out, int i, int k) {
    int r = i / k, c = i % k;
    float v = W[i];
    __nv_bfloat16 h = __float2bfloat16(v);
    __nv_bfloat16 l = __float2bfloat16(v - __bfloat162float(h));
    size_t base = (size_t)r * 3 * k;
    out[base + c] = h;
    out[base + k + c] = l;
    out[base + 2 * k + c] = h;
}

__global__ void __launch_bounds__(256) k_prep(const float* __restrict__ W1,
                                              const float* __restrict__ W2,
                                              const float* __restrict__ Wdec,
                                              int items) {
    int b = blockIdx.x;
    const int tid = threadIdx.x;
    if (b < 64) { g_counts[b * 256 + tid] = 0; return; }
    b -= 64;
    if (b < 512) { split_one(W1, g_W1s, b * 256 + tid, HDIM); return; }
    b -= 512;
    if (b < 512) { split_one(W2, g_W2s, b * 256 + tid, LATENT); return; }
    b -= 512;
    int i = b * 256 + tid;
    if (i < items * HDIM) g_Wdec16[i] = __float2half(Wdec[i]);
}

// ---------------- bucketing ----------------
__global__ void k_hist(const int* __restrict__ user, int n) {
    for (int i = blockIdx.x * blockDim.x + threadIdx.x; i < n; i += gridDim.x * blockDim.x)
        atomicAdd(&g_counts[user[i]], 1);
}

__global__ void __launch_bounds__(128) k_scanA() {
    const int b = blockIdx.x, t = threadIdx.x;
    const int lane = t & 31, w = t >> 5;
    int v = g_counts[b * 128 + t];
    int inc = v;
#pragma unroll
    for (int off = 1; off < 32; off <<= 1) {
        int s = __shfl_up_sync(0xffffffffu, inc, off);
        if (lane >= off) inc += s;
    }
    __shared__ int ws[4];
    if (lane == 31) ws[w] = inc;
    __syncthreads();
    int wbase = 0;
#pragma unroll
    for (int i = 0; i < 4; i++) if (i < w) wbase += ws[i];
    g_offsets[b * 128 + t] = wbase + inc - v;
    if (t == 127) g_bsum[b] = wbase + inc;
}

__global__ void __launch_bounds__(128) k_scanB() {
    const int t = threadIdx.x, lane = t & 31, w = t >> 5;
    int v = g_bsum[t];
    int inc = v;
#pragma unroll
    for (int off = 1; off < 32; off <<= 1) {
        int s = __shfl_up_sync(0xffffffffu, inc, off);
        if (lane >= off) inc += s;
    }
    __shared__ int ws[4];
    if (lane == 31) ws[w] = inc;
    __syncthreads();
    int wbase = 0;
#pragma unroll
    for (int i = 0; i < 4; i++) if (i < w) wbase += ws[i];
    g_bsumx[t] = wbase + inc - v;
}

__global__ void __launch_bounds__(128) k_scanC(int n) {
    const int b = blockIdx.x, t = threadIdx.x;
    const int i = b * 128 + t;
    int o = g_offsets[i] + g_bsumx[b];
    g_offsets[i] = o;
    g_cursor[i]  = o;
    if (i == 0) g_offsets[NUSERS] = n;
}

__global__ void k_scatter(const int* __restrict__ user, int n) {
    for (int i = blockIdx.x * blockDim.x + threadIdx.x; i < n; i += gridDim.x * blockDim.x) {
        int u = user[i];
        int pos = atomicAdd(&g_cursor[u], 1);
        g_idx[pos] = i;
    }
}

// ---------------- per-user segment sum + tanh(agg + b_enc) -> bf16 hi/lo ----------------
__global__ void __launch_bounds__(128) k_aggregate(const int* __restrict__ item,
                                                   const float* __restrict__ rating,
                                                   const float* __restrict__ b_enc) {
    const int u = blockIdx.x;
    const int tid = threadIdx.x;
    const int beg = g_offsets[u], end = g_offsets[u + 1];
    __shared__ int   s_idx[512];
    __shared__ int   s_it[512];
    __shared__ float s_r[512];
    float4 acc = make_float4(0.f, 0.f, 0.f, 0.f);
    const int h4 = tid * 4;
    for (int ch = beg; ch < end; ch += 512) {
        int c = min(512, end - ch);
        for (int i = tid; i < c; i += 128) s_idx[i] = g_idx[ch + i];
        __syncthreads();
        if (tid == 0) {
            for (int i = 1; i < c; i++) {
                int key = s_idx[i];
                int j = i - 1;
                while (j >= 0 && s_idx[j] > key) { s_idx[j + 1] = s_idx[j]; j--; }
                s_idx[j + 1] = key;
            }
        }
        __syncthreads();
        for (int i = tid; i < c; i += 128) {
            int nn = s_idx[i];
            s_it[i] = item[nn];
            s_r[i]  = rating[nn];
        }
        __syncthreads();
        for (int e = 0; e < c; e++) {
            const float4 w = *reinterpret_cast<const float4*>(&g_WencT[(size_t)s_it[e] * HDIM + h4]);
            float r = s_r[e];
            acc.x += r * w.x; acc.y += r * w.y; acc.z += r * w.z; acc.w += r * w.w;
        }
        __syncthreads();
    }
    float4 b = *reinterpret_cast<const float4*>(&b_enc[h4]);
    float t[4] = { tanhf(acc.x + b.x), tanhf(acc.y + b.y), tanhf(acc.z + b.z), tanhf(acc.w + b.w) };
    __nv_bfloat16 hv[4], lv[4];
#pragma unroll
    for (int j = 0; j < 4; j++) {
        hv[j] = __float2bfloat16(t[j]);
        lv[j] = __float2bfloat16(t[j] - __bfloat162float(hv[j]));
    }
    *reinterpret_cast<uint2*>(&g_xs[(size_t)u * 1024 + h4])       = *reinterpret_cast<uint2*>(hv);
    *reinterpret_cast<uint2*>(&g_xs[(size_t)u * 1024 + 512 + h4]) = *reinterpret_cast<uint2*>(lv);
}

// ---------------- mma.sync split-bf16 GEMM ----------------
// CTA tile 128x128, BK=32, 256 threads = 8 warps (4 m x 2 n), warp tile 32x64.
// OUTMODE 0: bf16 hi/lo pair -> Cb [M, 2*NTOT].  OUTMODE 1: fp16 -> Ch [M, NTOT].
#define SROW 40   // smem row stride in bf16 elements (80B, conflict-free for ldmatrix)
#define STAGE_B (128 * SROW * 2)  // bytes per stage

template <int KDIM, int ASTRIDE>
__device__ __forceinline__ void load_stage(const __nv_bfloat16* __restrict__ Ag,
                                           const __nv_bfloat16* __restrict__ Bg,
                                           int m0, int n0, int lr, int lg,
                                           uint32_t aBase, uint32_t bBase, int c, int s) {
    constexpr int KP = KDIM / 32;
    constexpr int BSTRIDE = 3 * KDIM;
    const int part = (c >= 2 * KP) ? 1 : 0;
    const int kofs = (c % KP) * 32;
    const __nv_bfloat16* Ap = Ag + (size_t)(m0 + lr) * ASTRIDE + part * KDIM + kofs + lg * 8;
    const __nv_bfloat16* Bp = Bg + (size_t)(n0 + lr) * BSTRIDE + c * 32 + lg * 8;
    uint32_t da = aBase + s * STAGE_B + (lr * SROW + lg * 8) * 2;
    uint32_t db = bBase + s * STAGE_B + (lr * SROW + lg * 8) * 2;
    cpasync16(da, Ap);      cpasync16(da + 16, Ap + 8);
    cpasync16(db, Bp);      cpasync16(db + 16, Bp + 8);
}

template <int KDIM, int ASTRIDE, int OUTMODE, int NTOT>
__global__ void __launch_bounds__(256) k_mma_gemm(const __nv_bfloat16* __restrict__ Ag,
                                                  const __nv_bfloat16* __restrict__ Bg,
                                                  const float* __restrict__ bias,
                                                  __half* __restrict__ Ch,
                                                  __nv_bfloat16* __restrict__ Cb) {
    constexpr int NCH = 3 * (KDIM / 32);
    __shared__ __align__(1024) __nv_bfloat16 sA[2][128 * SROW];
    __shared__ __align__(1024) __nv_bfloat16 sB[2][128 * SROW];

    const int tid = threadIdx.x;
    const int wid = tid >> 5, lane = tid & 31;
    const int wm = wid & 3, wn = wid >> 2;
    const int m0 = blockIdx.y * 128, n0 = blockIdx.x * 128;
    const int lr = tid >> 1;            // loader row 0..127
    const int lg = (tid & 1) * 2;       // loader quad base

    const uint32_t aBase = smem_u32(sA), bBase = smem_u32(sB);

    const int aRow = wm * 32 + (lane & 15);
    const int aKB  = (lane >> 4) * 16;
    const int bRow = wn * 64 + ((lane >> 4) * 8) + (lane & 7);
    const int bKB  = ((lane >> 3) & 1) * 16;

    float acc[2][8][4];
#pragma unroll
    for (int i = 0; i < 2; i++)
#pragma unroll
        for (int j = 0; j < 8; j++)
#pragma unroll
            for (int q = 0; q < 4; q++) acc[i][j][q] = 0.f;

    load_stage<KDIM, ASTRIDE>(Ag, Bg, m0, n0, lr, lg, aBase, bBase, 0, 0);
    cp_commit();

    for (int c = 0; c < NCH; c++) {
        const int s = c & 1;
        if (c + 1 < NCH) {
            load_stage<KDIM, ASTRIDE>(Ag, Bg, m0, n0, lr, lg, aBase, bBase, c + 1, s ^ 1);
            cp_commit();
            cp_wait<1>();
        } else {
            cp_wait<0>();
        }
        __syncthreads();

#pragma unroll
        for (int ks = 0; ks < 2; ks++) {
            uint32_t a[2][4];
#pragma unroll
            for (int mt = 0; mt < 2; mt++) {
                uint32_t addr = aBase + s * STAGE_B + ((aRow + mt * 16) * SROW) * 2 + ks * 32 + aKB;
                ldsm_x4(a[mt][0], a[mt][1], a[mt][2], a[mt][3], addr);
            }
            uint32_t b[8][2];
#pragma unroll
            for (int nt2 = 0; nt2 < 4; nt2++) {
                uint32_t addr = bBase + s * STAGE_B + ((bRow + nt2 * 16) * SROW) * 2 + ks * 32 + bKB;
                ldsm_x4(b[2 * nt2][0], b[2 * nt2][1], b[2 * nt2 + 1][0], b[2 * nt2 + 1][1], addr);
            }
#pragma unroll
            for (int mt = 0; mt < 2; mt++)
#pragma unroll
                for (int nt = 0; nt < 8; nt++)
                    mma_bf16(acc[mt][nt], a[mt][0], a[mt][1], a[mt][2], a[mt][3],
                             b[nt][0], b[nt][1]);
        }
        __syncthreads();
    }

    // epilogue
#pragma unroll
    for (int mt = 0; mt < 2; mt++) {
        const int mA = m0 + wm * 32 + mt * 16 + (lane >> 2);
#pragma unroll
        for (int nt = 0; nt < 8; nt++) {
            const int col = n0 + wn * 64 + nt * 8 + 2 * (lane & 3);
            const float b0 = __ldg(&bias[col]), b1 = __ldg(&bias[col + 1]);
#pragma unroll
            for (int half = 0; half < 2; half++) {
                const int m = mA + half * 8;
                const float t0 = tanhf(acc[mt][nt][2 * half + 0] + b0);
                const float t1 = tanhf(acc[mt][nt][2 * half + 1] + b1);
                if (OUTMODE == 0) {
                    __nv_bfloat16 h0 = __float2bfloat16(t0), h1 = __float2bfloat16(t1);
                    __nv_bfloat16 l0 = __float2bfloat16(t0 - __bfloat162float(h0));
                    __nv_bfloat16 l1 = __float2bfloat16(t1 - __bfloat162float(h1));
                    __nv_bfloat162 hp; hp.x = h0; hp.y = h1;
                    __nv_bfloat162 lp; lp.x = l0; lp.y = l1;
                    *reinterpret_cast<__nv_bfloat162*>(&Cb[(size_t)m * (2 * NTOT) + col]) = hp;
                    *reinterpret_cast<__nv_bfloat162*>(&Cb[(size_t)m * (2 * NTOT) + NTOT + col]) = lp;
                } else {
                    __half2 v; v.x = __float2half(t0); v.y = __float2half(t1);
                    *reinterpret_cast<__half2*>(&Ch[(size_t)m * NTOT + col]) = v;
                }
            }
        }
    }
}

// ---------------- prediction (fp16 gathers) + per-block squared-error partials -----------
__global__ void __launch_bounds__(256) k_pred(const int* __restrict__ tu,
                                              const int* __restrict__ ti,
                                              const float* __restrict__ tr,
                                              const float* __restrict__ bdec,
                                              float* __restrict__ out, int nt) {
    __shared__ float sh[8];
    const int gw = (blockIdx.x * 256 + threadIdx.x) >> 5;
    const int lane = threadIdx.x & 31;
    float se = 0.f;
    if (gw < nt) {
        int u  = tu[gw];
        int it = ti[gw];
        const uint4* g = reinterpret_cast<const uint4*>(&g_dec16[(size_t)u * HDIM]);
        const uint4* w = reinterpret_cast<const uint4*>(&g_Wdec16[(size_t)it * HDIM]);
        float s = 0.f;
#pragma unroll
        for (int q = 0; q < 2; q++) {
            uint4 av = g[lane + 32 * q];
            uint4 bv = w[lane + 32 * q];
            const __half2* ah = reinterpret_cast<const __half2*>(&av);
            const __half2* bh = reinterpret_cast<const __half2*>(&bv);
#pragma unroll
            for (int p = 0; p < 4; p++) {
                float2 af = __half22float2(ah[p]);
                float2 bf = __half22float2(bh[p]);
                s = fmaf(af.x, bf.x, s);
                s = fmaf(af.y, bf.y, s);
            }
        }
#pragma unroll
        for (int off = 16; off; off >>= 1) s += __shfl_down_sync(0xffffffffu, s, off);
        if (lane == 0) {
            float p = s + bdec[it];
            out[gw] = p;
            float d = p - tr[gw];
            se = d * d;
        }
    }
    if (lane == 0) sh[threadIdx.x >> 5] = se;
    __syncthreads();
    if (threadIdx.x == 0) {
        float t = 0.f;
#pragma unroll
        for (int i = 0; i < 8; i++) t += sh[i];
        g_partials[blockIdx.x] = t;
    }
}

__global__ void __launch_bounds__(1024) k_loss(float* __restrict__ loc, int nblocks, int nt) {
    __shared__ float sh[32];
    const int tid = threadIdx.x;
    float s = 0.f;
    for (int i = tid; i < nblocks; i += 1024) s += g_partials[i];
#pragma unroll
    for (int off = 16; off; off >>= 1) s += __shfl_down_sync(0xffffffffu, s, off);
    if ((tid & 31) == 0) sh[tid >> 5] = s;
    __syncthreads();
    if (tid < 32) {
        float v = sh[tid];
#pragma unroll
        for (int off = 16; off; off >>= 1) v += __shfl_down_sync(0xffffffffu, v, off);
        if (tid == 0) *loc = v / (float)nt;
    }
}

// ---------------- launch ----------------
extern "C" void kernel_launch(void* const* d_in, const int* in_sizes, int n_in,
                              void* d_out, int out_size) {
    const int*   user   = (const int*)d_in[0];
    const int*   item   = (const int*)d_in[1];
    const float* rating = (const float*)d_in[2];
    const int*   tuser  = (const int*)d_in[3];
    const int*   titem  = (const int*)d_in[4];
    const float* trat   = (const float*)d_in[5];
    const float* W_enc  = (const float*)d_in[6];
    const float* b_enc  = (const float*)d_in[7];
    const float* W1     = (const float*)d_in[8];
    const float* b1     = (const float*)d_in[9];
    const float* W2     = (const float*)d_in[10];
    const float* b2     = (const float*)d_in[11];
    const float* W_dec  = (const float*)d_in[12];
    const float* b_dec  = (const float*)d_in[13];

    const int N     = in_sizes[0];
    const int NT    = in_sizes[3];
    const int items = in_sizes[13];

    float* pred = (float*)d_out;

    // 1. fused prep (zero counts, split W1/W2, Wdec->fp16) + transpose
    {
        const int nb = 64 + 512 + 512 + (items * HDIM + 255) / 256;
        k_prep<<<nb, 256>>>(W1, W2, W_dec, items);
    }
    k_transpose<<<dim3((items + 31) / 32, HDIM / 32), dim3(32, 32)>>>(W_enc, items);

    // 2. bucket interactions by user
    k_hist<<<256, 256>>>(user, N);
    k_scanA<<<128, 128>>>();
    k_scanB<<<1, 128>>>();
    k_scanC<<<128, 128>>>(N);
    k_scatter<<<256, 256>>>(user, N);

    // 3. per-user segment sum + tanh(+b_enc) -> bf16 hi/lo
    k_aggregate<<<NUSERS, 128>>>(item, rating, b_enc);

    // 4. tensor-core (HMMA) split-bf16 GEMMs
    {
        __nv_bfloat16 *xs, *encs, *w1s, *w2s;
        __half* dec;
        cudaGetSymbolAddress((void**)&xs,   g_xs);
        cudaGetSymbolAddress((void**)&encs, g_encs);
        cudaGetSymbolAddress((void**)&w1s,  g_W1s);
        cudaGetSymbolAddress((void**)&w2s,  g_W2s);
        cudaGetSymbolAddress((void**)&dec,  g_dec16);
        k_mma_gemm<HDIM, 2 * HDIM, 0, LATENT><<<dim3(LATENT / 128, NUSERS / 128), 256>>>(
            xs, w1s, b1, nullptr, encs);
        k_mma_gemm<LATENT, 2 * LATENT, 1, HDIM><<<dim3(HDIM / 128, NUSERS / 128), 256>>>(
            encs, w2s, b2, dec, nullptr);
    }

    // 5. predictions + loss partials (fp16 gathers)
    const int npb = (NT + 7) / 8;
    k_pred<<<npb, 256>>>(tuser, titem, trat, b_dec, pred, NT);

    // 6. final loss
    if (out_size > NT)
        k_loss<<<1, 1024>>>(pred + NT, npb, NT);
}

// round 9
// speedup vs baseline: 1.5129x; 1.0231x over previous
#include <cuda_runtime.h>
#include <cuda_bf16.h>
#include <cuda_fp16.h>
#include <cstdint>
#include <cstddef>
#include <math.h>

#define NUSERS 16384
#define HDIM 512
#define LATENT 256
#define MAX_ITEMS 50176
#define MAX_N (1 << 19)

// ---------------- device scratch (no allocation allowed) ----------------
__device__ __align__(128) float g_WencT[(size_t)MAX_ITEMS * HDIM];
__device__ __align__(128) __nv_bfloat16 g_xs[(size_t)NUSERS * (2 * HDIM)];     // [xh(512) | xl(512)]
__device__ __align__(128) __nv_bfloat16 g_encs[(size_t)NUSERS * (2 * LATENT)]; // [eh(256) | el(256)]
__device__ __align__(128) __nv_bfloat16 g_W1s[(size_t)LATENT * (3 * HDIM)];    // [wh | wl | wh]
__device__ __align__(128) __nv_bfloat16 g_W2s[(size_t)HDIM * (3 * LATENT)];
__device__ __align__(128) __half g_dec16[(size_t)NUSERS * HDIM];
__device__ __align__(128) __half g_Wdec16[(size_t)MAX_ITEMS * HDIM];
__device__ int   g_counts[NUSERS + 2];   // [NUSERS]=scan done-counter, [NUSERS+1]=release flag
__device__ int   g_offsets[NUSERS + 1];
__device__ int   g_cursor[NUSERS];
__device__ int   g_idx[MAX_N];
__device__ int   g_bsum[128];
__device__ int   g_bsumx[128];
__device__ float g_partials[MAX_N / 8 + 64];

// ---------------- PTX helpers (arch-neutral: sm_80+ features only) ----------------
__device__ __forceinline__ uint32_t smem_u32(const void* p) {
    uint32_t a;
    asm("{ .reg .u64 t; cvta.to.shared.u64 t, %1; cvt.u32.u64 %0, t; }" : "=r"(a) : "l"(p));
    return a;
}
__device__ __forceinline__ void cpasync16(uint32_t dst, const void* src) {
    asm volatile("cp.async.cg.shared.global [%0], [%1], 16;" :: "r"(dst), "l"(src) : "memory");
}
__device__ __forceinline__ void cp_commit() {
    asm volatile("cp.async.commit_group;" ::: "memory");
}
template <int NREM>
__device__ __forceinline__ void cp_wait() {
    asm volatile("cp.async.wait_group %0;" :: "n"(NREM) : "memory");
}
__device__ __forceinline__ void ldsm_x4(uint32_t& r0, uint32_t& r1, uint32_t& r2, uint32_t& r3,
                                        uint32_t addr) {
    asm volatile("ldmatrix.sync.aligned.m8n8.x4.shared.b16 {%0,%1,%2,%3}, [%4];"
                 : "=r"(r0), "=r"(r1), "=r"(r2), "=r"(r3) : "r"(addr));
}
__device__ __forceinline__ void mma_bf16(float* c, uint32_t a0, uint32_t a1, uint32_t a2, uint32_t a3,
                                         uint32_t b0, uint32_t b1) {
    asm volatile("mma.sync.aligned.m16n8k16.row.col.f32.bf16.bf16.f32 "
                 "{%0,%1,%2,%3}, {%4,%5,%6,%7}, {%8,%9}, {%0,%1,%2,%3};"
                 : "+f"(c[0]), "+f"(c[1]), "+f"(c[2]), "+f"(c[3])
                 : "r"(a0), "r"(a1), "r"(a2), "r"(a3), "r"(b0), "r"(b1));
}

// ---------------- transpose W_enc [512][items] -> g_WencT [items][512] ----------------
__global__ void k_transpose(const float* __restrict__ W, int items) {
    __shared__ float tile[32][33];
    int i = blockIdx.x * 32 + threadIdx.x;
    int h = blockIdx.y * 32 + threadIdx.y;
    if (i < items)
        tile[threadIdx.y][threadIdx.x] = W[(size_t)h * items + i];
    __syncthreads();
    int io = blockIdx.x * 32 + threadIdx.y;
    int ho = blockIdx.y * 32 + threadIdx.x;
    if (io < items)
        g_WencT[(size_t)io * HDIM + ho] = tile[threadIdx.x][threadIdx.y];
}

// ---------------- weight prep: split W1/W2 to bf16 hi/lo, Wdec -> fp16 ----------------
__device__ __forceinline__ void split_one(const float* __restrict__ W,
                                          __nv_bfloat16* __restrict__ out, int i, int k) {
    int r = i / k, c = i % k;
    float v = W[i];
    __nv_bfloat16 h = __float2bfloat16(v);
    __nv_bfloat16 l = __float2bfloat16(v - __bfloat162float(h));
    size_t base = (size_t)r * 3 * k;
    out[base + c] = h;
    out[base + k + c] = l;
    out[base + 2 * k + c] = h;
}

__global__ void __launch_bounds__(256) k_prep_w(const float* __restrict__ W1,
                                                const float* __restrict__ W2,
                                                const float* __restrict__ Wdec,
                                                int items) {
    int b = blockIdx.x;
    const int tid = threadIdx.x;
    if (b < 512) { split_one(W1, g_W1s, b * 256 + tid, HDIM); return; }
    b -= 512;
    if (b < 512) { split_one(W2, g_W2s, b * 256 + tid, LATENT); return; }
    b -= 512;
    int i = b * 256 + tid;
    if (i < items * HDIM) g_Wdec16[i] = __float2half(Wdec[i]);
}

// ---------------- bucketing ----------------
__global__ void k_hist(const int* __restrict__ user, int n) {
    for (int i = blockIdx.x * blockDim.x + threadIdx.x; i < n; i += gridDim.x * blockDim.x)
        atomicAdd(&g_counts[user[i]], 1);
}

// single-pass scan of g_counts[16384]: 128 resident blocks, last block does middle scan
__global__ void __launch_bounds__(128) k_scan_fused(int n) {
    const int b = blockIdx.x, t = threadIdx.x;
    const int lane = t & 31, w = t >> 5;
    __shared__ int ws[4], ws2[4];
    __shared__ int s_last;

    int v = g_counts[b * 128 + t];
    int inc = v;
#pragma unroll
    for (int off = 1; off < 32; off <<= 1) {
        int s = __shfl_up_sync(0xffffffffu, inc, off);
        if (lane >= off) inc += s;
    }
    if (lane == 31) ws[w] = inc;
    __syncthreads();
    int wbase = 0;
#pragma unroll
    for (int i = 0; i < 4; i++) if (i < w) wbase += ws[i];
    const int lexcl = wbase + inc - v;
    if (t == 127) g_bsum[b] = wbase + inc;
    __threadfence();
    if (t == 0) s_last = (atomicAdd(&g_counts[NUSERS], 1) == 127) ? 1 : 0;
    __syncthreads();

    if (s_last) {
        __threadfence();
        int v2 = g_bsum[t];
        int inc2 = v2;
#pragma unroll
        for (int off = 1; off < 32; off <<= 1) {
            int s = __shfl_up_sync(0xffffffffu, inc2, off);
            if (lane >= off) inc2 += s;
        }
        if (lane == 31) ws2[w] = inc2;
        __syncthreads();
        int wb2 = 0;
#pragma unroll
        for (int i = 0; i < 4; i++) if (i < w) wb2 += ws2[i];
        g_bsumx[t] = wb2 + inc2 - v2;
        __threadfence();
        __syncthreads();
        if (t == 0) atomicExch(&g_counts[NUSERS + 1], 1);
    }

    if (t == 0) {
        while (atomicAdd(&g_counts[NUSERS + 1], 0) == 0) {}
    }
    __syncthreads();
    __threadfence();

    const int i = b * 128 + t;
    const int o = lexcl + g_bsumx[b];
    g_offsets[i] = o;
    g_cursor[i]  = o;
    if (i == 0) g_offsets[NUSERS] = n;
}

__global__ void k_scatter(const int* __restrict__ user, int n) {
    for (int i = blockIdx.x * blockDim.x + threadIdx.x; i < n; i += gridDim.x * blockDim.x) {
        int u = user[i];
        int pos = atomicAdd(&g_cursor[u], 1);
        g_idx[pos] = i;
    }
}

// ---------------- per-user segment sum + tanh(agg + b_enc) -> bf16 hi/lo ----------------
__global__ void __launch_bounds__(128) k_aggregate(const int* __restrict__ item,
                                                   const float* __restrict__ rating,
                                                   const float* __restrict__ b_enc) {
    const int u = blockIdx.x;
    const int tid = threadIdx.x;
    const int beg = g_offsets[u], end = g_offsets[u + 1];
    __shared__ int   s_idx[512];
    __shared__ int   s_it[512];
    __shared__ float s_r[512];
    float4 acc = make_float4(0.f, 0.f, 0.f, 0.f);
    const int h4 = tid * 4;
    for (int ch = beg; ch < end; ch += 512) {
        int c = min(512, end - ch);
        for (int i = tid; i < c; i += 128) s_idx[i] = g_idx[ch + i];
        __syncthreads();
        if (tid == 0) {
            for (int i = 1; i < c; i++) {
                int key = s_idx[i];
                int j = i - 1;
                while (j >= 0 && s_idx[j] > key) { s_idx[j + 1] = s_idx[j]; j--; }
                s_idx[j + 1] = key;
            }
        }
        __syncthreads();
        for (int i = tid; i < c; i += 128) {
            int nn = s_idx[i];
            s_it[i] = item[nn];
            s_r[i]  = rating[nn];
        }
        __syncthreads();
        for (int e = 0; e < c; e++) {
            const float4 w = *reinterpret_cast<const float4*>(&g_WencT[(size_t)s_it[e] * HDIM + h4]);
            float r = s_r[e];
            acc.x += r * w.x; acc.y += r * w.y; acc.z += r * w.z; acc.w += r * w.w;
        }
        __syncthreads();
    }
    float4 b = *reinterpret_cast<const float4*>(&b_enc[h4]);
    float t[4] = { tanhf(acc.x + b.x), tanhf(acc.y + b.y), tanhf(acc.z + b.z), tanhf(acc.w + b.w) };
    __nv_bfloat16 hv[4], lv[4];
#pragma unroll
    for (int j = 0; j < 4; j++) {
        hv[j] = __float2bfloat16(t[j]);
        lv[j] = __float2bfloat16(t[j] - __bfloat162float(hv[j]));
    }
    *reinterpret_cast<uint2*>(&g_xs[(size_t)u * 1024 + h4])       = *reinterpret_cast<uint2*>(hv);
    *reinterpret_cast<uint2*>(&g_xs[(size_t)u * 1024 + 512 + h4]) = *reinterpret_cast<uint2*>(lv);
}

// ---------------- mma.sync split-bf16 GEMM ----------------
// CTA tile 128x128, BK=32, 256 threads = 8 warps (4 m x 2 n), warp tile 32x64.
// OUTMODE 0: bf16 hi/lo pair -> Cb [M, 2*NTOT].  OUTMODE 1: fp16 -> Ch [M, NTOT].
#define SROW 40   // smem row stride in bf16 elements (80B, conflict-free for ldmatrix)
#define STAGE_B (128 * SROW * 2)  // bytes per stage

template <int KDIM, int ASTRIDE>
__device__ __forceinline__ void load_stage(const __nv_bfloat16* __restrict__ Ag,
                                           const __nv_bfloat16* __restrict__ Bg,
                                           int m0, int n0, int lr, int lg,
                                           uint32_t aBase, uint32_t bBase, int c, int s) {
    constexpr int KP = KDIM / 32;
    constexpr int BSTRIDE = 3 * KDIM;
    const int part = (c >= 2 * KP) ? 1 : 0;
    const int kofs = (c % KP) * 32;
    const __nv_bfloat16* Ap = Ag + (size_t)(m0 + lr) * ASTRIDE + part * KDIM + kofs + lg * 8;
    const __nv_bfloat16* Bp = Bg + (size_t)(n0 + lr) * BSTRIDE + c * 32 + lg * 8;
    uint32_t da = aBase + s * STAGE_B + (lr * SROW + lg * 8) * 2;
    uint32_t db = bBase + s * STAGE_B + (lr * SROW + lg * 8) * 2;
    cpasync16(da, Ap);      cpasync16(da + 16, Ap + 8);
    cpasync16(db, Bp);      cpasync16(db + 16, Bp + 8);
}

template <int KDIM, int ASTRIDE, int OUTMODE, int NTOT>
__global__ void __launch_bounds__(256) k_mma_gemm(const __nv_bfloat16* __restrict__ Ag,
                                                  const __nv_bfloat16* __restrict__ Bg,
                                                  const float* __restrict__ bias,
                                                  __half* __restrict__ Ch,
                                                  __nv_bfloat16* __restrict__ Cb) {
    constexpr int NCH = 3 * (KDIM / 32);
    __shared__ __align__(1024) __nv_bfloat16 sA[2][128 * SROW];
    __shared__ __align__(1024) __nv_bfloat16 sB[2][128 * SROW];

    const int tid = threadIdx.x;
    const int wid = tid >> 5, lane = tid & 31;
    const int wm = wid & 3, wn = wid >> 2;
    const int m0 = blockIdx.y * 128, n0 = blockIdx.x * 128;
    const int lr = tid >> 1;            // loader row 0..127
    const int lg = (tid & 1) * 2;       // loader quad base

    const uint32_t aBase = smem_u32(sA), bBase = smem_u32(sB);

    const int aRow = wm * 32 + (lane & 15);
    const int aKB  = (lane >> 4) * 16;
    const int bRow = wn * 64 + ((lane >> 4) * 8) + (lane & 7);
    const int bKB  = ((lane >> 3) & 1) * 16;

    float acc[2][8][4];
#pragma unroll
    for (int i = 0; i < 2; i++)
#pragma unroll
        for (int j = 0; j < 8; j++)
#pragma unroll
            for (int q = 0; q < 4; q++) acc[i][j][q] = 0.f;

    load_stage<KDIM, ASTRIDE>(Ag, Bg, m0, n0, lr, lg, aBase, bBase, 0, 0);
    cp_commit();

    for (int c = 0; c < NCH; c++) {
        const int s = c & 1;
        if (c + 1 < NCH) {
            load_stage<KDIM, ASTRIDE>(Ag, Bg, m0, n0, lr, lg, aBase, bBase, c + 1, s ^ 1);
            cp_commit();
            cp_wait<1>();
        } else {
            cp_wait<0>();
        }
        __syncthreads();

#pragma unroll
        for (int ks = 0; ks < 2; ks++) {
            uint32_t a[2][4];
#pragma unroll
            for (int mt = 0; mt < 2; mt++) {
                uint32_t addr = aBase + s * STAGE_B + ((aRow + mt * 16) * SROW) * 2 + ks * 32 + aKB;
                ldsm_x4(a[mt][0], a[mt][1], a[mt][2], a[mt][3], addr);
            }
            uint32_t b[8][2];
#pragma unroll
            for (int nt2 = 0; nt2 < 4; nt2++) {
                uint32_t addr = bBase + s * STAGE_B + ((bRow + nt2 * 16) * SROW) * 2 + ks * 32 + bKB;
                ldsm_x4(b[2 * nt2][0], b[2 * nt2][1], b[2 * nt2 + 1][0], b[2 * nt2 + 1][1], addr);
            }
#pragma unroll
            for (int mt = 0; mt < 2; mt++)
#pragma unroll
                for (int nt = 0; nt < 8; nt++)
                    mma_bf16(acc[mt][nt], a[mt][0], a[mt][1], a[mt][2], a[mt][3],
                             b[nt][0], b[nt][1]);
        }
        __syncthreads();
    }

    // epilogue
#pragma unroll
    for (int mt = 0; mt < 2; mt++) {
        const int mA = m0 + wm * 32 + mt * 16 + (lane >> 2);
#pragma unroll
        for (int nt = 0; nt < 8; nt++) {
            const int col = n0 + wn * 64 + nt * 8 + 2 * (lane & 3);
            const float b0 = __ldg(&bias[col]), b1 = __ldg(&bias[col + 1]);
#pragma unroll
            for (int half = 0; half < 2; half++) {
                const int m = mA + half * 8;
                const float t0 = tanhf(acc[mt][nt][2 * half + 0] + b0);
                const float t1 = tanhf(acc[mt][nt][2 * half + 1] + b1);
                if (OUTMODE == 0) {
                    __nv_bfloat16 h0 = __float2bfloat16(t0), h1 = __float2bfloat16(t1);
                    __nv_bfloat16 l0 = __float2bfloat16(t0 - __bfloat162float(h0));
                    __nv_bfloat16 l1 = __float2bfloat16(t1 - __bfloat162float(h1));
                    __nv_bfloat162 hp; hp.x = h0; hp.y = h1;
                    __nv_bfloat162 lp; lp.x = l0; lp.y = l1;
                    *reinterpret_cast<__nv_bfloat162*>(&Cb[(size_t)m * (2 * NTOT) + col]) = hp;
                    *reinterpret_cast<__nv_bfloat162*>(&Cb[(size_t)m * (2 * NTOT) + NTOT + col]) = lp;
                } else {
                    __half2 v; v.x = __float2half(t0); v.y = __float2half(t1);
                    *reinterpret_cast<__half2*>(&Ch[(size_t)m * NTOT + col]) = v;
                }
            }
        }
    }
}

// ---------------- prediction (fp16 gathers) + per-block squared-error partials -----------
__global__ void __launch_bounds__(256) k_pred(const int* __restrict__ tu,
                                              const int* __restrict__ ti,
                                              const float* __restrict__ tr,
                                              const float* __restrict__ bdec,
                                              float* __restrict__ out, int nt) {
    __shared__ float sh[8];
    const int gw = (blockIdx.x * 256 + threadIdx.x) >> 5;
    const int lane = threadIdx.x & 31;
    float se = 0.f;
    if (gw < nt) {
        int u  = tu[gw];
        int it = ti[gw];
        const uint4* g = reinterpret_cast<const uint4*>(&g_dec16[(size_t)u * HDIM]);
        const uint4* w = reinterpret_cast<const uint4*>(&g_Wdec16[(size_t)it * HDIM]);
        float s = 0.f;
#pragma unroll
        for (int q = 0; q < 2; q++) {
            uint4 av = g[lane + 32 * q];
            uint4 bv = w[lane + 32 * q];
            const __half2* ah = reinterpret_cast<const __half2*>(&av);
            const __half2* bh = reinterpret_cast<const __half2*>(&bv);
#pragma unroll
            for (int p = 0; p < 4; p++) {
                float2 af = __half22float2(ah[p]);
                float2 bf = __half22float2(bh[p]);
                s = fmaf(af.x, bf.x, s);
                s = fmaf(af.y, bf.y, s);
            }
        }
#pragma unroll
        for (int off = 16; off; off >>= 1) s += __shfl_down_sync(0xffffffffu, s, off);
        if (lane == 0) {
            float p = s + bdec[it];
            out[gw] = p;
            float d = p - tr[gw];
            se = d * d;
        }
    }
    if (lane == 0) sh[threadIdx.x >> 5] = se;
    __syncthreads();
    if (threadIdx.x == 0) {
        float t = 0.f;
#pragma unroll
        for (int i = 0; i < 8; i++) t += sh[i];
        g_partials[blockIdx.x] = t;
    }
}

__global__ void __launch_bounds__(1024) k_loss(float* __restrict__ loc, int nblocks, int nt) {
    __shared__ float sh[32];
    const int tid = threadIdx.x;
    float s = 0.f;
    for (int i = tid; i < nblocks; i += 1024) s += g_partials[i];
#pragma unroll
    for (int off = 16; off; off >>= 1) s += __shfl_down_sync(0xffffffffu, s, off);
    if ((tid & 31) == 0) sh[tid >> 5] = s;
    __syncthreads();
    if (tid < 32) {
        float v = sh[tid];
#pragma unroll
        for (int off = 16; off; off >>= 1) v += __shfl_down_sync(0xffffffffu, v, off);
        if (tid == 0) *loc = v / (float)nt;
    }
}

// ---------------- launch ----------------
extern "C" void kernel_launch(void* const* d_in, const int* in_sizes, int n_in,
                              void* d_out, int out_size) {
    const int*   user   = (const int*)d_in[0];
    const int*   item   = (const int*)d_in[1];
    const float* rating = (const float*)d_in[2];
    const int*   tuser  = (const int*)d_in[3];
    const int*   titem  = (const int*)d_in[4];
    const float* trat   = (const float*)d_in[5];
    const float* W_enc  = (const float*)d_in[6];
    const float* b_enc  = (const float*)d_in[7];
    const float* W1     = (const float*)d_in[8];
    const float* b1     = (const float*)d_in[9];
    const float* W2     = (const float*)d_in[10];
    const float* b2     = (const float*)d_in[11];
    const float* W_dec  = (const float*)d_in[12];
    const float* b_dec  = (const float*)d_in[13];

    const int N     = in_sizes[0];
    const int NT    = in_sizes[3];
    const int items = in_sizes[13];

    float* pred = (float*)d_out;

    // side streams + fork-join events (created/destroyed per call; graph keeps only deps)
    cudaStream_t s1, s2;
    cudaEvent_t evRoot, e1, e2;
    cudaStreamCreateWithFlags(&s1, cudaStreamNonBlocking);
    cudaStreamCreateWithFlags(&s2, cudaStreamNonBlocking);
    cudaEventCreateWithFlags(&evRoot, cudaEventDisableTiming);
    cudaEventCreateWithFlags(&e1, cudaEventDisableTiming);
    cudaEventCreateWithFlags(&e2, cudaEventDisableTiming);

    // fork
    cudaEventRecord(evRoot, 0);
    cudaStreamWaitEvent(s1, evRoot, 0);
    cudaStreamWaitEvent(s2, evRoot, 0);

    // branch 1: weight prep (splits + Wdec->fp16)
    {
        const int nb = 512 + 512 + (items * HDIM + 255) / 256;
        k_prep_w<<<nb, 256, 0, s1>>>(W1, W2, W_dec, items);
    }
    // branch 2: encoder weight transpose
    k_transpose<<<dim3((items + 31) / 32, HDIM / 32), dim3(32, 32), 0, s2>>>(W_enc, items);

    // main branch: bucketing
    {
        int* cptr;
        cudaGetSymbolAddress((void**)&cptr, g_counts);
        cudaMemsetAsync(cptr, 0, (NUSERS + 2) * sizeof(int), 0);
    }
    k_hist<<<256, 256>>>(user, N);
    k_scan_fused<<<128, 128>>>(N);
    k_scatter<<<256, 256>>>(user, N);

    // join: aggregate needs transpose + scatter (and GEMMs need prep_w)
    cudaEventRecord(e1, s1);
    cudaEventRecord(e2, s2);
    cudaStreamWaitEvent(0, e1, 0);
    cudaStreamWaitEvent(0, e2, 0);

    // 3. per-user segment sum + tanh(+b_enc) -> bf16 hi/lo
    k_aggregate<<<NUSERS, 128>>>(item, rating, b_enc);

    // 4. tensor-core (HMMA) split-bf16 GEMMs
    {
        __nv_bfloat16 *xs, *encs, *w1s, *w2s;
        __half* dec;
        cudaGetSymbolAddress((void**)&xs,   g_xs);
        cudaGetSymbolAddress((void**)&encs, g_encs);
        cudaGetSymbolAddress((void**)&w1s,  g_W1s);
        cudaGetSymbolAddress((void**)&w2s,  g_W2s);
        cudaGetSymbolAddress((void**)&dec,  g_dec16);
        k_mma_gemm<HDIM, 2 * HDIM, 0, LATENT><<<dim3(LATENT / 128, NUSERS / 128), 256>>>(
            xs, w1s, b1, nullptr, encs);
        k_mma_gemm<LATENT, 2 * LATENT, 1, HDIM><<<dim3(HDIM / 128, NUSERS / 128), 256>>>(
            encs, w2s, b2, dec, nullptr);
    }

    // 5. predictions + loss partials (fp16 gathers)
    const int npb = (NT + 7) / 8;
    k_pred<<<npb, 256>>>(tuser, titem, trat, b_dec, pred, NT);

    // 6. final loss
    if (out_size > NT)
        k_loss<<<1, 1024>>>(pred + NT, npb, NT);

    cudaEventDestroy(evRoot);
    cudaEventDestroy(e1);
    cudaEventDestroy(e2);
    cudaStreamDestroy(s1);
    cudaStreamDestroy(s2);
}

// round 10
// speedup vs baseline: 1.5949x; 1.0541x over previous
#include <cuda_runtime.h>
#include <cuda_bf16.h>
#include <cuda_fp16.h>
#include <cstdint>
#include <cstddef>
#include <math.h>

#define NUSERS 16384
#define HDIM 512
#define LATENT 256
#define MAX_ITEMS 50176
#define MAX_N (1 << 19)

// ---------------- device scratch (no allocation allowed) ----------------
__device__ __align__(128) __half g_WencT16[(size_t)MAX_ITEMS * HDIM];          // fp16 transposed enc weights
__device__ __align__(128) __nv_bfloat16 g_xs[(size_t)NUSERS * (2 * HDIM)];     // [xh(512) | xl(512)]
__device__ __align__(128) __nv_bfloat16 g_encs[(size_t)NUSERS * (2 * LATENT)]; // [eh(256) | el(256)]
__device__ __align__(128) __nv_bfloat16 g_W1s[(size_t)LATENT * (3 * HDIM)];    // [wh | wl | wh]
__device__ __align__(128) __nv_bfloat16 g_W2s[(size_t)HDIM * (3 * LATENT)];
__device__ __align__(128) __half g_dec16[(size_t)NUSERS * HDIM];
__device__ __align__(128) __half g_Wdec16[(size_t)MAX_ITEMS * HDIM];
__device__ int   g_counts[NUSERS + 2];   // [NUSERS]=scan done-counter, [NUSERS+1]=release flag
__device__ int   g_offsets[NUSERS + 1];
__device__ int   g_cursor[NUSERS];
__device__ int   g_idx[MAX_N];
__device__ int   g_bsum[128];
__device__ int   g_bsumx[128];
__device__ float g_partials[MAX_N / 8 + 64];

// ---------------- PTX helpers (arch-neutral: sm_80+ features only) ----------------
__device__ __forceinline__ uint32_t smem_u32(const void* p) {
    uint32_t a;
    asm("{ .reg .u64 t; cvta.to.shared.u64 t, %1; cvt.u32.u64 %0, t; }" : "=r"(a) : "l"(p));
    return a;
}
__device__ __forceinline__ void cpasync16(uint32_t dst, const void* src) {
    asm volatile("cp.async.cg.shared.global [%0], [%1], 16;" :: "r"(dst), "l"(src) : "memory");
}
__device__ __forceinline__ void cp_commit() {
    asm volatile("cp.async.commit_group;" ::: "memory");
}
template <int NREM>
__device__ __forceinline__ void cp_wait() {
    asm volatile("cp.async.wait_group %0;" :: "n"(NREM) : "memory");
}
__device__ __forceinline__ void ldsm_x4(uint32_t& r0, uint32_t& r1, uint32_t& r2, uint32_t& r3,
                                        uint32_t addr) {
    asm volatile("ldmatrix.sync.aligned.m8n8.x4.shared.b16 {%0,%1,%2,%3}, [%4];"
                 : "=r"(r0), "=r"(r1), "=r"(r2), "=r"(r3) : "r"(addr));
}
__device__ __forceinline__ void mma_bf16(float* c, uint32_t a0, uint32_t a1, uint32_t a2, uint32_t a3,
                                         uint32_t b0, uint32_t b1) {
    asm volatile("mma.sync.aligned.m16n8k16.row.col.f32.bf16.bf16.f32 "
                 "{%0,%1,%2,%3}, {%4,%5,%6,%7}, {%8,%9}, {%0,%1,%2,%3};"
                 : "+f"(c[0]), "+f"(c[1]), "+f"(c[2]), "+f"(c[3])
                 : "r"(a0), "r"(a1), "r"(a2), "r"(a3), "r"(b0), "r"(b1));
}

// ---------------- transpose W_enc [512][items] -> g_WencT16 [items][512] (fp16) -----------
__global__ void k_transpose(const float* __restrict__ W, int items) {
    __shared__ float tile[32][33];
    int i = blockIdx.x * 32 + threadIdx.x;
    int h = blockIdx.y * 32 + threadIdx.y;
    if (i < items)
        tile[threadIdx.y][threadIdx.x] = W[(size_t)h * items + i];
    __syncthreads();
    int io = blockIdx.x * 32 + threadIdx.y;
    int ho = blockIdx.y * 32 + threadIdx.x;
    if (io < items)
        g_WencT16[(size_t)io * HDIM + ho] = __float2half(tile[threadIdx.x][threadIdx.y]);
}

// ---------------- weight prep: split W1/W2 to bf16 hi/lo, Wdec -> fp16 ----------------
__device__ __forceinline__ void split_one(const float* __restrict__ W,
                                          __nv_bfloat16* __restrict__ out, int i, int k) {
    int r = i / k, c = i % k;
    float v = W[i];
    __nv_bfloat16 h = __float2bfloat16(v);
    __nv_bfloat16 l = __float2bfloat16(v - __bfloat162float(h));
    size_t base = (size_t)r * 3 * k;
    out[base + c] = h;
    out[base + k + c] = l;
    out[base + 2 * k + c] = h;
}

__global__ void __launch_bounds__(256) k_prep_w(const float* __restrict__ W1,
                                                const float* __restrict__ W2,
                                                const float* __restrict__ Wdec,
                                                int items) {
    int b = blockIdx.x;
    const int tid = threadIdx.x;
    if (b < 512) { split_one(W1, g_W1s, b * 256 + tid, HDIM); return; }
    b -= 512;
    if (b < 512) { split_one(W2, g_W2s, b * 256 + tid, LATENT); return; }
    b -= 512;
    int i = b * 256 + tid;
    if (i < items * HDIM) g_Wdec16[i] = __float2half(Wdec[i]);
}

// ---------------- bucketing ----------------
__global__ void k_hist(const int* __restrict__ user, int n) {
    for (int i = blockIdx.x * blockDim.x + threadIdx.x; i < n; i += gridDim.x * blockDim.x)
        atomicAdd(&g_counts[user[i]], 1);
}

// single-pass scan of g_counts[16384]: 128 resident blocks, last block does middle scan
__global__ void __launch_bounds__(128) k_scan_fused(int n) {
    const int b = blockIdx.x, t = threadIdx.x;
    const int lane = t & 31, w = t >> 5;
    __shared__ int ws[4], ws2[4];
    __shared__ int s_last;

    int v = g_counts[b * 128 + t];
    int inc = v;
#pragma unroll
    for (int off = 1; off < 32; off <<= 1) {
        int s = __shfl_up_sync(0xffffffffu, inc, off);
        if (lane >= off) inc += s;
    }
    if (lane == 31) ws[w] = inc;
    __syncthreads();
    int wbase = 0;
#pragma unroll
    for (int i = 0; i < 4; i++) if (i < w) wbase += ws[i];
    const int lexcl = wbase + inc - v;
    if (t == 127) g_bsum[b] = wbase + inc;
    __threadfence();
    if (t == 0) s_last = (atomicAdd(&g_counts[NUSERS], 1) == 127) ? 1 : 0;
    __syncthreads();

    if (s_last) {
        __threadfence();
        int v2 = g_bsum[t];
        int inc2 = v2;
#pragma unroll
        for (int off = 1; off < 32; off <<= 1) {
            int s = __shfl_up_sync(0xffffffffu, inc2, off);
            if (lane >= off) inc2 += s;
        }
        if (lane == 31) ws2[w] = inc2;
        __syncthreads();
        int wb2 = 0;
#pragma unroll
        for (int i = 0; i < 4; i++) if (i < w) wb2 += ws2[i];
        g_bsumx[t] = wb2 + inc2 - v2;
        __threadfence();
        __syncthreads();
        if (t == 0) atomicExch(&g_counts[NUSERS + 1], 1);
    }

    if (t == 0) {
        while (atomicAdd(&g_counts[NUSERS + 1], 0) == 0) {}
    }
    __syncthreads();
    __threadfence();

    const int i = b * 128 + t;
    const int o = lexcl + g_bsumx[b];
    g_offsets[i] = o;
    g_cursor[i]  = o;
    if (i == 0) g_offsets[NUSERS] = n;
}

__global__ void k_scatter(const int* __restrict__ user, int n) {
    for (int i = blockIdx.x * blockDim.x + threadIdx.x; i < n; i += gridDim.x * blockDim.x) {
        int u = user[i];
        int pos = atomicAdd(&g_cursor[u], 1);
        g_idx[pos] = i;
    }
}

// ---------------- per-user segment sum (fp16 table) + tanh(agg+b) -> bf16 hi/lo ----------
__global__ void __launch_bounds__(128) k_aggregate(const int* __restrict__ item,
                                                   const float* __restrict__ rating,
                                                   const float* __restrict__ b_enc) {
    const int u = blockIdx.x;
    const int tid = threadIdx.x;
    const int beg = g_offsets[u], end = g_offsets[u + 1];
    __shared__ int   s_idx[512];
    __shared__ int   s_it[512];
    __shared__ float s_r[512];
    float4 acc = make_float4(0.f, 0.f, 0.f, 0.f);
    const int h4 = tid * 4;
    for (int ch = beg; ch < end; ch += 512) {
        int c = min(512, end - ch);
        for (int i = tid; i < c; i += 128) s_idx[i] = g_idx[ch + i];
        __syncthreads();
        if (tid == 0) {
            for (int i = 1; i < c; i++) {
                int key = s_idx[i];
                int j = i - 1;
                while (j >= 0 && s_idx[j] > key) { s_idx[j + 1] = s_idx[j]; j--; }
                s_idx[j + 1] = key;
            }
        }
        __syncthreads();
        for (int i = tid; i < c; i += 128) {
            int nn = s_idx[i];
            s_it[i] = item[nn];
            s_r[i]  = rating[nn];
        }
        __syncthreads();
        for (int e = 0; e < c; e++) {
            uint2 raw = *reinterpret_cast<const uint2*>(&g_WencT16[(size_t)s_it[e] * HDIM + h4]);
            const __half2* wh = reinterpret_cast<const __half2*>(&raw);
            float2 f01 = __half22float2(wh[0]);
            float2 f23 = __half22float2(wh[1]);
            float r = s_r[e];
            acc.x = fmaf(r, f01.x, acc.x);
            acc.y = fmaf(r, f01.y, acc.y);
            acc.z = fmaf(r, f23.x, acc.z);
            acc.w = fmaf(r, f23.y, acc.w);
        }
        __syncthreads();
    }
    float4 b = *reinterpret_cast<const float4*>(&b_enc[h4]);
    float t[4] = { tanhf(acc.x + b.x), tanhf(acc.y + b.y), tanhf(acc.z + b.z), tanhf(acc.w + b.w) };
    __nv_bfloat16 hv[4], lv[4];
#pragma unroll
    for (int j = 0; j < 4; j++) {
        hv[j] = __float2bfloat16(t[j]);
        lv[j] = __float2bfloat16(t[j] - __bfloat162float(hv[j]));
    }
    *reinterpret_cast<uint2*>(&g_xs[(size_t)u * 1024 + h4])       = *reinterpret_cast<uint2*>(hv);
    *reinterpret_cast<uint2*>(&g_xs[(size_t)u * 1024 + 512 + h4]) = *reinterpret_cast<uint2*>(lv);
}

// ---------------- mma.sync split-bf16 GEMM ----------------
// CTA tile 128x128, BK=32, 256 threads = 8 warps (4 m x 2 n), warp tile 32x64.
// OUTMODE 0: bf16 hi/lo pair -> Cb [M, 2*NTOT].  OUTMODE 1: fp16 -> Ch [M, NTOT].
#define SROW 40   // smem row stride in bf16 elements (80B, conflict-free for ldmatrix)
#define STAGE_B (128 * SROW * 2)  // bytes per stage

template <int KDIM, int ASTRIDE>
__device__ __forceinline__ void load_stage(const __nv_bfloat16* __restrict__ Ag,
                                           const __nv_bfloat16* __restrict__ Bg,
                                           int m0, int n0, int lr, int lg,
                                           uint32_t aBase, uint32_t bBase, int c, int s) {
    constexpr int KP = KDIM / 32;
    constexpr int BSTRIDE = 3 * KDIM;
    const int part = (c >= 2 * KP) ? 1 : 0;
    const int kofs = (c % KP) * 32;
    const __nv_bfloat16* Ap = Ag + (size_t)(m0 + lr) * ASTRIDE + part * KDIM + kofs + lg * 8;
    const __nv_bfloat16* Bp = Bg + (size_t)(n0 + lr) * BSTRIDE + c * 32 + lg * 8;
    uint32_t da = aBase + s * STAGE_B + (lr * SROW + lg * 8) * 2;
    uint32_t db = bBase + s * STAGE_B + (lr * SROW + lg * 8) * 2;
    cpasync16(da, Ap);      cpasync16(da + 16, Ap + 8);
    cpasync16(db, Bp);      cpasync16(db + 16, Bp + 8);
}

template <int KDIM, int ASTRIDE, int OUTMODE, int NTOT>
__global__ void __launch_bounds__(256) k_mma_gemm(const __nv_bfloat16* __restrict__ Ag,
                                                  const __nv_bfloat16* __restrict__ Bg,
                                                  const float* __restrict__ bias,
                                                  __half* __restrict__ Ch,
                                                  __nv_bfloat16* __restrict__ Cb) {
    constexpr int NCH = 3 * (KDIM / 32);
    __shared__ __align__(1024) __nv_bfloat16 sA[2][128 * SROW];
    __shared__ __align__(1024) __nv_bfloat16 sB[2][128 * SROW];

    const int tid = threadIdx.x;
    const int wid = tid >> 5, lane = tid & 31;
    const int wm = wid & 3, wn = wid >> 2;
    const int m0 = blockIdx.y * 128, n0 = blockIdx.x * 128;
    const int lr = tid >> 1;            // loader row 0..127
    const int lg = (tid & 1) * 2;       // loader quad base

    const uint32_t aBase = smem_u32(sA), bBase = smem_u32(sB);

    const int aRow = wm * 32 + (lane & 15);
    const int aKB  = (lane >> 4) * 16;
    const int bRow = wn * 64 + ((lane >> 4) * 8) + (lane & 7);
    const int bKB  = ((lane >> 3) & 1) * 16;

    float acc[2][8][4];
#pragma unroll
    for (int i = 0; i < 2; i++)
#pragma unroll
        for (int j = 0; j < 8; j++)
#pragma unroll
            for (int q = 0; q < 4; q++) acc[i][j][q] = 0.f;

    load_stage<KDIM, ASTRIDE>(Ag, Bg, m0, n0, lr, lg, aBase, bBase, 0, 0);
    cp_commit();

    for (int c = 0; c < NCH; c++) {
        const int s = c & 1;
        if (c + 1 < NCH) {
            load_stage<KDIM, ASTRIDE>(Ag, Bg, m0, n0, lr, lg, aBase, bBase, c + 1, s ^ 1);
            cp_commit();
            cp_wait<1>();
        } else {
            cp_wait<0>();
        }
        __syncthreads();

#pragma unroll
        for (int ks = 0; ks < 2; ks++) {
            uint32_t a[2][4];
#pragma unroll
            for (int mt = 0; mt < 2; mt++) {
                uint32_t addr = aBase + s * STAGE_B + ((aRow + mt * 16) * SROW) * 2 + ks * 32 + aKB;
                ldsm_x4(a[mt][0], a[mt][1], a[mt][2], a[mt][3], addr);
            }
            uint32_t b[8][2];
#pragma unroll
            for (int nt2 = 0; nt2 < 4; nt2++) {
                uint32_t addr = bBase + s * STAGE_B + ((bRow + nt2 * 16) * SROW) * 2 + ks * 32 + bKB;
                ldsm_x4(b[2 * nt2][0], b[2 * nt2][1], b[2 * nt2 + 1][0], b[2 * nt2 + 1][1], addr);
            }
#pragma unroll
            for (int mt = 0; mt < 2; mt++)
#pragma unroll
                for (int nt = 0; nt < 8; nt++)
                    mma_bf16(acc[mt][nt], a[mt][0], a[mt][1], a[mt][2], a[mt][3],
                             b[nt][0], b[nt][1]);
        }
        __syncthreads();
    }

    // epilogue
#pragma unroll
    for (int mt = 0; mt < 2; mt++) {
        const int mA = m0 + wm * 32 + mt * 16 + (lane >> 2);
#pragma unroll
        for (int nt = 0; nt < 8; nt++) {
            const int col = n0 + wn * 64 + nt * 8 + 2 * (lane & 3);
            const float b0 = __ldg(&bias[col]), b1 = __ldg(&bias[col + 1]);
#pragma unroll
            for (int half = 0; half < 2; half++) {
                const int m = mA + half * 8;
                const float t0 = tanhf(acc[mt][nt][2 * half + 0] + b0);
                const float t1 = tanhf(acc[mt][nt][2 * half + 1] + b1);
                if (OUTMODE == 0) {
                    __nv_bfloat16 h0 = __float2bfloat16(t0), h1 = __float2bfloat16(t1);
                    __nv_bfloat16 l0 = __float2bfloat16(t0 - __bfloat162float(h0));
                    __nv_bfloat16 l1 = __float2bfloat16(t1 - __bfloat162float(h1));
                    __nv_bfloat162 hp; hp.x = h0; hp.y = h1;
                    __nv_bfloat162 lp; lp.x = l0; lp.y = l1;
                    *reinterpret_cast<__nv_bfloat162*>(&Cb[(size_t)m * (2 * NTOT) + col]) = hp;
                    *reinterpret_cast<__nv_bfloat162*>(&Cb[(size_t)m * (2 * NTOT) + NTOT + col]) = lp;
                } else {
                    __half2 v; v.x = __float2half(t0); v.y = __float2half(t1);
                    *reinterpret_cast<__half2*>(&Ch[(size_t)m * NTOT + col]) = v;
                }
            }
        }
    }
}

// ---------------- prediction (fp16 gathers) + per-block squared-error partials -----------
__global__ void __launch_bounds__(256) k_pred(const int* __restrict__ tu,
                                              const int* __restrict__ ti,
                                              const float* __restrict__ tr,
                                              const float* __restrict__ bdec,
                                              float* __restrict__ out, int nt) {
    __shared__ float sh[8];
    const int gw = (blockIdx.x * 256 + threadIdx.x) >> 5;
    const int lane = threadIdx.x & 31;
    float se = 0.f;
    if (gw < nt) {
        int u  = tu[gw];
        int it = ti[gw];
        const uint4* g = reinterpret_cast<const uint4*>(&g_dec16[(size_t)u * HDIM]);
        const uint4* w = reinterpret_cast<const uint4*>(&g_Wdec16[(size_t)it * HDIM]);
        float s = 0.f;
#pragma unroll
        for (int q = 0; q < 2; q++) {
            uint4 av = g[lane + 32 * q];
            uint4 bv = w[lane + 32 * q];
            const __half2* ah = reinterpret_cast<const __half2*>(&av);
            const __half2* bh = reinterpret_cast<const __half2*>(&bv);
#pragma unroll
            for (int p = 0; p < 4; p++) {
                float2 af = __half22float2(ah[p]);
                float2 bf = __half22float2(bh[p]);
                s = fmaf(af.x, bf.x, s);
                s = fmaf(af.y, bf.y, s);
            }
        }
#pragma unroll
        for (int off = 16; off; off >>= 1) s += __shfl_down_sync(0xffffffffu, s, off);
        if (lane == 0) {
            float p = s + bdec[it];
            out[gw] = p;
            float d = p - tr[gw];
            se = d * d;
        }
    }
    if (lane == 0) sh[threadIdx.x >> 5] = se;
    __syncthreads();
    if (threadIdx.x == 0) {
        float t = 0.f;
#pragma unroll
        for (int i = 0; i < 8; i++) t += sh[i];
        g_partials[blockIdx.x] = t;
    }
}

__global__ void __launch_bounds__(1024) k_loss(float* __restrict__ loc, int nblocks, int nt) {
    __shared__ float sh[32];
    const int tid = threadIdx.x;
    float s = 0.f;
    for (int i = tid; i < nblocks; i += 1024) s += g_partials[i];
#pragma unroll
    for (int off = 16; off; off >>= 1) s += __shfl_down_sync(0xffffffffu, s, off);
    if ((tid & 31) == 0) sh[tid >> 5] = s;
    __syncthreads();
    if (tid < 32) {
        float v = sh[tid];
#pragma unroll
        for (int off = 16; off; off >>= 1) v += __shfl_down_sync(0xffffffffu, v, off);
        if (tid == 0) *loc = v / (float)nt;
    }
}

// ---------------- launch ----------------
extern "C" void kernel_launch(void* const* d_in, const int* in_sizes, int n_in,
                              void* d_out, int out_size) {
    const int*   user   = (const int*)d_in[0];
    const int*   item   = (const int*)d_in[1];
    const float* rating = (const float*)d_in[2];
    const int*   tuser  = (const int*)d_in[3];
    const int*   titem  = (const int*)d_in[4];
    const float* trat   = (const float*)d_in[5];
    const float* W_enc  = (const float*)d_in[6];
    const float* b_enc  = (const float*)d_in[7];
    const float* W1     = (const float*)d_in[8];
    const float* b1     = (const float*)d_in[9];
    const float* W2     = (const float*)d_in[10];
    const float* b2     = (const float*)d_in[11];
    const float* W_dec  = (const float*)d_in[12];
    const float* b_dec  = (const float*)d_in[13];

    const int N     = in_sizes[0];
    const int NT    = in_sizes[3];
    const int items = in_sizes[13];

    float* pred = (float*)d_out;

    // side streams + fork-join events
    cudaStream_t s1, s2;
    cudaEvent_t evRoot, e1, e2;
    cudaStreamCreateWithFlags(&s1, cudaStreamNonBlocking);
    cudaStreamCreateWithFlags(&s2, cudaStreamNonBlocking);
    cudaEventCreateWithFlags(&evRoot, cudaEventDisableTiming);
    cudaEventCreateWithFlags(&e1, cudaEventDisableTiming);
    cudaEventCreateWithFlags(&e2, cudaEventDisableTiming);

    // fork
    cudaEventRecord(evRoot, 0);
    cudaStreamWaitEvent(s1, evRoot, 0);
    cudaStreamWaitEvent(s2, evRoot, 0);

    // branch 1: weight prep (splits + Wdec->fp16)
    {
        const int nb = 512 + 512 + (items * HDIM + 255) / 256;
        k_prep_w<<<nb, 256, 0, s1>>>(W1, W2, W_dec, items);
    }
    // branch 2: encoder weight transpose (fp32 -> fp16)
    k_transpose<<<dim3((items + 31) / 32, HDIM / 32), dim3(32, 32), 0, s2>>>(W_enc, items);

    // main branch: bucketing
    {
        int* cptr;
        cudaGetSymbolAddress((void**)&cptr, g_counts);
        cudaMemsetAsync(cptr, 0, (NUSERS + 2) * sizeof(int), 0);
    }
    k_hist<<<256, 256>>>(user, N);
    k_scan_fused<<<128, 128>>>(N);
    k_scatter<<<256, 256>>>(user, N);

    // join
    cudaEventRecord(e1, s1);
    cudaEventRecord(e2, s2);
    cudaStreamWaitEvent(0, e1, 0);
    cudaStreamWaitEvent(0, e2, 0);

    // 3. per-user segment sum (fp16 table) + tanh(+b_enc) -> bf16 hi/lo
    k_aggregate<<<NUSERS, 128>>>(item, rating, b_enc);

    // 4. tensor-core (HMMA) split-bf16 GEMMs
    {
        __nv_bfloat16 *xs, *encs, *w1s, *w2s;
        __half* dec;
        cudaGetSymbolAddress((void**)&xs,   g_xs);
        cudaGetSymbolAddress((void**)&encs, g_encs);
        cudaGetSymbolAddress((void**)&w1s,  g_W1s);
        cudaGetSymbolAddress((void**)&w2s,  g_W2s);
        cudaGetSymbolAddress((void**)&dec,  g_dec16);
        k_mma_gemm<HDIM, 2 * HDIM, 0, LATENT><<<dim3(LATENT / 128, NUSERS / 128), 256>>>(
            xs, w1s, b1, nullptr, encs);
        k_mma_gemm<LATENT, 2 * LATENT, 1, HDIM><<<dim3(HDIM / 128, NUSERS / 128), 256>>>(
            encs, w2s, b2, dec, nullptr);
    }

    // 5. predictions + loss partials (fp16 gathers)
    const int npb = (NT + 7) / 8;
    k_pred<<<npb, 256>>>(tuser, titem, trat, b_dec, pred, NT);

    // 6. final loss
    if (out_size > NT)
        k_loss<<<1, 1024>>>(pred + NT, npb, NT);

    cudaEventDestroy(evRoot);
    cudaEventDestroy(e1);
    cudaEventDestroy(e2);
    cudaStreamDestroy(s1);
    cudaStreamDestroy(s2);
}